// round 12
// baseline (speedup 1.0000x reference)
#include <cuda_runtime.h>
#include <cuda_bf16.h>
#include <math.h>
#include <stdint.h>

#define T_STEPS 512
#define BATCH   64
#define DH      1024
#define DIN     1024
#define NROWS   (T_STEPS * BATCH)        // 32768

__device__ unsigned g_bar;
// bf16 split of x (hi/lo), produced by split_kernel
__device__ __nv_bfloat16 g_xh[(size_t)NROWS * DIN];
__device__ __nv_bfloat16 g_xl[(size_t)NROWS * DIN];

// ---------------------------------------------------------------------------
// Split kernel: fp32 -> (hi, lo) bf16 pair.  a = hi + lo + O(2^-16 |a|)
// ---------------------------------------------------------------------------
__global__ void __launch_bounds__(256) split_kernel(
    const float* __restrict__ src,
    __nv_bfloat16* __restrict__ hi, __nv_bfloat16* __restrict__ lo, int n4)
{
    for (int i = blockIdx.x * blockDim.x + threadIdx.x; i < n4;
         i += gridDim.x * blockDim.x) {
        const float4 v = ((const float4*)src)[i];
        const __nv_bfloat16 h0 = __float2bfloat16(v.x);
        const __nv_bfloat16 h1 = __float2bfloat16(v.y);
        const __nv_bfloat16 h2 = __float2bfloat16(v.z);
        const __nv_bfloat16 h3 = __float2bfloat16(v.w);
        const __nv_bfloat16 l0 = __float2bfloat16(v.x - __bfloat162float(h0));
        const __nv_bfloat16 l1 = __float2bfloat16(v.y - __bfloat162float(h1));
        const __nv_bfloat16 l2 = __float2bfloat16(v.z - __bfloat162float(h2));
        const __nv_bfloat16 l3 = __float2bfloat16(v.w - __bfloat162float(h3));
        __nv_bfloat162* H = (__nv_bfloat162*)hi;
        __nv_bfloat162* L = (__nv_bfloat162*)lo;
        H[2 * i]     = __halves2bfloat162(h0, h1);
        H[2 * i + 1] = __halves2bfloat162(h2, h3);
        L[2 * i]     = __halves2bfloat162(l0, l1);
        L[2 * i + 1] = __halves2bfloat162(l2, l3);
    }
}

__device__ __forceinline__ void mma_bf16(
    float& c0, float& c1, float& c2, float& c3,
    uint32_t a0, uint32_t a1, uint32_t a2, uint32_t a3,
    uint32_t b0, uint32_t b1)
{
    asm volatile(
        "mma.sync.aligned.m16n8k16.row.col.f32.bf16.bf16.f32 "
        "{%0,%1,%2,%3}, {%4,%5,%6,%7}, {%8,%9}, {%0,%1,%2,%3};"
        : "+f"(c0), "+f"(c1), "+f"(c2), "+f"(c3)
        : "r"(a0), "r"(a1), "r"(a2), "r"(a3), "r"(b0), "r"(b1));
}

// ---------------------------------------------------------------------------
// FUSED persistent kernel: recurrence (FMA pipe) + next-step input projection
// (tensor pipe, mma.sync bf16 split-3) in the same blocks.
//
// 128 blocks x 512 threads. Block jb owns h-cols [8jb,8jb+8). Its gate inputs
// are proj cols {8jb..} of each of w_cx/w_ix/w_fx = 64x24 tile = 12 warp
// mma-tiles (4 m16 x 3 n8), computed for step t+1 while step t's GEMV runs.
// Proj results stay in smem (pbuf double buffer) — no DRAM for ct/ix/fx.
// ---------------------------------------------------------------------------
#define RBLOCKS   128
#define RTHREADS  512
#define HS_STRIDE 68
#define HS_TILE   (64 * HS_STRIDE)
// smem byte offsets
#define OFF_WI    0                         // [8][1024] f32
#define OFF_WF    32768                     // [8][1024] f32
#define OFF_HS    65536                     // 2 x [64][68] f32
#define OFF_PWH   100352                    // [24][1032] bf16
#define OFF_PWL   149888                    // [24][1032] bf16
#define OFF_XH    199424                    // [64][72] bf16
#define OFF_XL    208640                    // [64][72] bf16
#define OFF_PB    217856                    // 2 x [64][25] f32
#define FSMEM     230656
#define PW_STR    1032
#define XS_STR    72
#define PB_STR    25

// Proj stage: 4 k16 steps of split-3 mma into pacc. Uses scope locals.
#define PROJ_STAGE(sbase) do {                                               \
    _Pragma("unroll")                                                        \
    for (int k4 = 0; k4 < 4; k4++) {                                         \
        const int kl = k4 * 16 + tg * 2;                                     \
        const int kg = (sbase) * 64 + k4 * 16 + tg * 2;                      \
        const int ar0 = (pmt * 16 + g) * XS_STR;                             \
        const uint32_t ah0 = *(const uint32_t*)(pxh + ar0 + kl);             \
        const uint32_t ah1 = *(const uint32_t*)(pxh + ar0 + 8 * XS_STR + kl);\
        const uint32_t ah2 = *(const uint32_t*)(pxh + ar0 + kl + 8);         \
        const uint32_t ah3 = *(const uint32_t*)(pxh + ar0 + 8 * XS_STR + kl + 8);\
        const uint32_t al0 = *(const uint32_t*)(pxl + ar0 + kl);             \
        const uint32_t al1 = *(const uint32_t*)(pxl + ar0 + 8 * XS_STR + kl);\
        const uint32_t al2 = *(const uint32_t*)(pxl + ar0 + kl + 8);         \
        const uint32_t al3 = *(const uint32_t*)(pxl + ar0 + 8 * XS_STR + kl + 8);\
        const int br0 = (pnt * 8 + g) * PW_STR;                              \
        const uint32_t bh0 = *(const uint32_t*)(pwh + br0 + kg);             \
        const uint32_t bh1 = *(const uint32_t*)(pwh + br0 + kg + 8);         \
        const uint32_t bl0 = *(const uint32_t*)(pwl + br0 + kg);             \
        const uint32_t bl1 = *(const uint32_t*)(pwl + br0 + kg + 8);         \
        mma_bf16(pacc[0], pacc[1], pacc[2], pacc[3], ah0, ah1, ah2, ah3, bh0, bh1);\
        mma_bf16(pacc[0], pacc[1], pacc[2], pacc[3], ah0, ah1, ah2, ah3, bl0, bl1);\
        mma_bf16(pacc[0], pacc[1], pacc[2], pacc[3], al0, al1, al2, al3, bh0, bh1);\
    }                                                                        \
} while (0)

__global__ void __launch_bounds__(RTHREADS) fused_kernel(
    const float* __restrict__ h0,
    const float* __restrict__ w_ic, const float* __restrict__ w_fc,
    const float* __restrict__ b_ic, const float* __restrict__ b_fc,
    const float* __restrict__ w_cx, const float* __restrict__ w_ix,
    const float* __restrict__ w_fx,
    const float* __restrict__ b_cx, const float* __restrict__ b_ix,
    const float* __restrict__ b_fx,
    float* __restrict__ out)
{
    extern __shared__ __align__(16) char smc[];
    float* wi_s = (float*)(smc + OFF_WI);
    float* wf_s = (float*)(smc + OFF_WF);
    float* hs0  = (float*)(smc + OFF_HS);
    float* hs1  = hs0 + HS_TILE;
    __nv_bfloat16* pwh = (__nv_bfloat16*)(smc + OFF_PWH);
    __nv_bfloat16* pwl = (__nv_bfloat16*)(smc + OFF_PWL);
    __nv_bfloat16* pxh = (__nv_bfloat16*)(smc + OFF_XH);
    __nv_bfloat16* pxl = (__nv_bfloat16*)(smc + OFF_XL);
    float* pb = (float*)(smc + OFF_PB);      // [2][64][25]

    const int tid  = threadIdx.x;
    const int wid  = tid >> 5;
    const int lane = tid & 31;
    const int kc   = tid >> 6;
    const int cg   = (tid >> 4) & 3;
    const int rg   = tid & 15;
    const int jb   = blockIdx.x;
    const int c0   = cg * 2;
    const int colg = jb * 8 + c0;
    const int lid  = cg * 16 + rg;

    // ---- load recurrence weights (f32) ----
    {
        const float4* gi = (const float4*)(w_ic + (size_t)jb * 8 * DH);
        const float4* gf = (const float4*)(w_fc + (size_t)jb * 8 * DH);
        float4* si = (float4*)wi_s;
        float4* sf = (float4*)wf_s;
        for (int i = tid; i < 8 * DH / 4; i += RTHREADS) { si[i] = gi[i]; sf[i] = gf[i]; }
    }
    // ---- split proj weights (24 rows: gate*8+r -> w_gate row 8jb+r) ----
    for (int i = tid; i < 24 * 256; i += RTHREADS) {
        const int n = i >> 8;                // 0..23
        const int o = (i & 255) * 4;
        const int gate = n >> 3, r = n & 7;
        const float* ws = (gate == 0 ? w_cx : (gate == 1 ? w_ix : w_fx))
                          + (size_t)(jb * 8 + r) * DIN + o;
        const float4 v = *(const float4*)ws;
        __nv_bfloat16* dh = pwh + n * PW_STR + o;
        __nv_bfloat16* dl = pwl + n * PW_STR + o;
        const float vv[4] = {v.x, v.y, v.z, v.w};
#pragma unroll
        for (int q = 0; q < 4; q++) {
            const __nv_bfloat16 h = __float2bfloat16(vv[q]);
            dh[q] = h;
            dl[q] = __float2bfloat16(vv[q] - __bfloat162float(h));
        }
    }
    const float* wiA = wi_s + (size_t)c0 * DH;
    const float* wiB = wi_s + (size_t)(c0 + 1) * DH;
    const float* wfA = wf_s + (size_t)c0 * DH;
    const float* wfB = wf_s + (size_t)(c0 + 1) * DH;
    const float biA = b_ic[colg], biB = b_ic[colg + 1];
    const float bfA = b_fc[colg], bfB = b_fc[colg + 1];

    // ---- proj warp setup ----
    const int g  = lane >> 2;
    const int tg = lane & 3;
    const int pmt = wid & 3;                 // m-tile
    const int pnt = wid >> 2;                // n-tile (gate), valid wid<12
    float pacc[4] = {0.f, 0.f, 0.f, 0.f};
    float pbias0 = 0.f, pbias1 = 0.f;
    if (wid < 12) {
        const float* bg = (pnt == 0) ? b_cx : ((pnt == 1) ? b_ix : b_fx);
        pbias0 = bg[jb * 8 + tg * 2];
        pbias1 = bg[jb * 8 + tg * 2 + 1];
    }
    __syncthreads();                          // weights + pw ready

    // xs fill mapping: 1 uint4 (8 bf16) per thread per buffer per stage
    const int xr = tid >> 3;                 // 0..63
    const int xq = (tid & 7) * 8;            // bf16 offset

    // ---- prologue: proj for t=0 into pb[0] ----
#pragma unroll 1
    for (int s = 0; s < 16; s++) {
        const uint4 vh = *(const uint4*)(g_xh + (size_t)xr * DIN + s * 64 + xq);
        const uint4 vl = *(const uint4*)(g_xl + (size_t)xr * DIN + s * 64 + xq);
        if (s) __syncthreads();              // prior stage's mma reads done
        *(uint4*)(pxh + xr * XS_STR + xq) = vh;
        *(uint4*)(pxl + xr * XS_STR + xq) = vl;
        __syncthreads();
        if (wid < 12) PROJ_STAGE(s);
    }
    if (wid < 12) {
        const int prow = pmt * 16 + g;
        const int pcol = pnt * 8 + tg * 2;
        float* d = pb + prow * PB_STR + pcol;
        d[0] = pacc[0] + pbias0;  d[1] = pacc[1] + pbias1;
        d[8 * PB_STR] = pacc[2] + pbias0;  d[8 * PB_STR + 1] = pacc[3] + pbias1;
        pacc[0] = pacc[1] = pacc[2] = pacc[3] = 0.f;
    }
    __syncthreads();                          // xs reads done before t-loop refill

    const unsigned nb = gridDim.x;
    const float* hprev = h0;

    const int frow0 = tid >> 4;
    const int frow1 = (tid + RTHREADS) >> 4;
    const int fq    = (tid & 15) * 4;
    const int rdoff = rg * HS_STRIDE + kc * 8;

#pragma unroll 1
    for (int t = 0; t < T_STEPS; t++) {
        float accI[2][4], accF[2][4];
#pragma unroll
        for (int c = 0; c < 2; c++)
#pragma unroll
            for (int m = 0; m < 4; m++) { accI[c][m] = 0.f; accF[c][m] = 0.f; }

        const size_t ob = (size_t)t * (BATCH * DH);
        const size_t xbase = (size_t)((t + 1 < T_STEPS) ? (t + 1) : (T_STEPS - 1)) * 64;

        // epilogue hprev prefetch
        float2 e_hp[4];
        if (kc == 0) {
#pragma unroll
            for (int m = 0; m < 4; m++)
                e_hp[m] = *(const float2*)(hprev + (size_t)(rg + 16 * m) * DH + colg);
        }

        // stage 0 fill (h tile + x tile for t+1)
        float4 pf0 = *(const float4*)(hprev + (size_t)frow0 * DH + fq);
        float4 pf1 = *(const float4*)(hprev + (size_t)frow1 * DH + fq);
        uint4 vh = *(const uint4*)(g_xh + (xbase + xr) * DIN + xq);
        uint4 vl = *(const uint4*)(g_xl + (xbase + xr) * DIN + xq);
        *(float4*)(hs0 + frow0 * HS_STRIDE + fq) = pf0;
        *(float4*)(hs0 + frow1 * HS_STRIDE + fq) = pf1;
        *(uint4*)(pxh + xr * XS_STR + xq) = vh;
        *(uint4*)(pxl + xr * XS_STR + xq) = vl;
        __syncthreads();

#pragma unroll 1
        for (int s = 0; s < 16; s++) {
            const float* cur = (s & 1) ? hs1 : hs0;
            float* nxt = (s & 1) ? hs0 : hs1;

            if (s < 15) {   // global prefetch for next stage
                pf0 = *(const float4*)(hprev + (size_t)frow0 * DH + (s + 1) * 64 + fq);
                pf1 = *(const float4*)(hprev + (size_t)frow1 * DH + (s + 1) * 64 + fq);
                vh = *(const uint4*)(g_xh + (xbase + xr) * DIN + (s + 1) * 64 + xq);
                vl = *(const uint4*)(g_xl + (xbase + xr) * DIN + (s + 1) * 64 + xq);
            }

            // ---- recurrence FMA block (unchanged, verified) ----
            const int kb = s * 64 + kc * 8;
            const float* cb = cur + rdoff;
#pragma unroll
            for (int j4 = 0; j4 < 2; j4++) {
                const float4 h0v = *(const float4*)(cb + j4 * 4 + 0 * 16 * HS_STRIDE);
                const float4 h1v = *(const float4*)(cb + j4 * 4 + 1 * 16 * HS_STRIDE);
                const float4 h2v = *(const float4*)(cb + j4 * 4 + 2 * 16 * HS_STRIDE);
                const float4 h3v = *(const float4*)(cb + j4 * 4 + 3 * 16 * HS_STRIDE);
                const float4 wiAv = *(const float4*)(wiA + kb + j4 * 4);
                const float4 wiBv = *(const float4*)(wiB + kb + j4 * 4);
                const float4 wfAv = *(const float4*)(wfA + kb + j4 * 4);
                const float4 wfBv = *(const float4*)(wfB + kb + j4 * 4);
                const float hm[4][4] = {{h0v.x, h0v.y, h0v.z, h0v.w},
                                        {h1v.x, h1v.y, h1v.z, h1v.w},
                                        {h2v.x, h2v.y, h2v.z, h2v.w},
                                        {h3v.x, h3v.y, h3v.z, h3v.w}};
                const float wa[4] = {wiAv.x, wiAv.y, wiAv.z, wiAv.w};
                const float wb[4] = {wiBv.x, wiBv.y, wiBv.z, wiBv.w};
                const float wc[4] = {wfAv.x, wfAv.y, wfAv.z, wfAv.w};
                const float wd[4] = {wfBv.x, wfBv.y, wfBv.z, wfBv.w};
#pragma unroll
                for (int j = 0; j < 4; j++)
#pragma unroll
                    for (int m = 0; m < 4; m++) {
                        accI[0][m] += hm[m][j] * wa[j];
                        accI[1][m] += hm[m][j] * wb[j];
                        accF[0][m] += hm[m][j] * wc[j];
                        accF[1][m] += hm[m][j] * wd[j];
                    }
            }

            // ---- proj mma for step t+1 (tensor pipe) ----
            if (wid < 12) PROJ_STAGE(s);

            if (s < 15) {
                __syncthreads();    // xs readers done before overwrite
                *(float4*)(nxt + frow0 * HS_STRIDE + fq) = pf0;
                *(float4*)(nxt + frow1 * HS_STRIDE + fq) = pf1;
                *(uint4*)(pxh + xr * XS_STR + xq) = vh;
                *(uint4*)(pxl + xr * XS_STR + xq) = vl;
                __syncthreads();
            }
        }

        // ---- write proj(t+1) results to pbuf[(t+1)&1] ----
        if (wid < 12) {
            const int prow = pmt * 16 + g;
            const int pcol = pnt * 8 + tg * 2;
            float* d = pb + ((t + 1) & 1) * 64 * PB_STR + prow * PB_STR + pcol;
            d[0] = pacc[0] + pbias0;  d[1] = pacc[1] + pbias1;
            d[8 * PB_STR] = pacc[2] + pbias0;  d[8 * PB_STR + 1] = pacc[3] + pbias1;
            pacc[0] = pacc[1] = pacc[2] = pacc[3] = 0.f;
        }

        // ---- kc reduction through smem (hs scratch) ----
        __syncthreads();
        if (kc > 0) {
            float* r = hs0 + ((kc - 1) * 64 + lid) * 17;
#pragma unroll
            for (int c = 0; c < 2; c++)
#pragma unroll
                for (int m = 0; m < 4; m++) {
                    r[c * 4 + m]     = accI[c][m];
                    r[8 + c * 4 + m] = accF[c][m];
                }
        }
        __syncthreads();

        if (kc == 0) {
#pragma unroll
            for (int rk = 0; rk < 7; rk++) {
                const float* r = hs0 + (rk * 64 + lid) * 17;
#pragma unroll
                for (int c = 0; c < 2; c++)
#pragma unroll
                    for (int m = 0; m < 4; m++) {
                        accI[c][m] += r[c * 4 + m];
                        accF[c][m] += r[8 + c * 4 + m];
                    }
            }
            const float* pbt = pb + (t & 1) * 64 * PB_STR;
#pragma unroll
            for (int m = 0; m < 4; m++) {
                const int row = rg + 16 * m;
                const size_t base = ob + (size_t)row * DH + colg;
                const float php[2] = {e_hp[m].x, e_hp[m].y};
#pragma unroll
                for (int c = 0; c < 2; c++) {
                    const int lc = c0 + c;
                    const float pct = pbt[row * PB_STR + lc];
                    const float pix = pbt[row * PB_STR + 8 + lc];
                    const float pfx = pbt[row * PB_STR + 16 + lc];
                    const float bi = c ? biB : biA;
                    const float bf = c ? bfB : bfA;
                    const float pi = accI[c][m] + bi + pix;
                    const float pv = accF[c][m] + bf + pfx;
                    const float ig = 1.f / (1.f + expf(-pi));
                    const float fg = 1.f / (1.f + expf(-pv));
                    const float cc = ig * pct + fg * php[c];
                    const float hn = tanhf(cc);
                    out[base + c] = hn;
                    if (t == T_STEPS - 1) {
                        const size_t tb = (size_t)T_STEPS * BATCH * DH;
                        out[tb + (size_t)row * DH + colg + c] = hn;
                    }
                }
            }
        }

        // ---- grid-wide barrier ----
        __threadfence();
        __syncthreads();
        if (tid == 0) {
            atomicAdd(&g_bar, 1u);
            const unsigned target = (unsigned)(t + 1) * nb;
            while (*((volatile unsigned*)&g_bar) < target) { }
            __threadfence();
        }
        __syncthreads();

        hprev = out + ob;
    }
}

// ---------------------------------------------------------------------------
extern "C" void kernel_launch(void* const* d_in, const int* in_sizes, int n_in,
                              void* d_out, int out_size)
{
    const float* x    = (const float*)d_in[0];
    const float* h0   = (const float*)d_in[1];
    const float* w_cx = (const float*)d_in[2];
    const float* w_ic = (const float*)d_in[3];
    const float* w_ix = (const float*)d_in[4];
    const float* w_fc = (const float*)d_in[5];
    const float* w_fx = (const float*)d_in[6];
    const float* b_cx = (const float*)d_in[7];
    const float* b_ic = (const float*)d_in[8];
    const float* b_ix = (const float*)d_in[9];
    const float* b_fc = (const float*)d_in[10];
    const float* b_fx = (const float*)d_in[11];
    float* out = (float*)d_out;

    // reset grid-barrier counter
    void* barAddr = nullptr;
    cudaGetSymbolAddress(&barAddr, g_bar);
    cudaMemsetAsync(barAddr, 0, sizeof(unsigned), 0);

    void *xh, *xl;
    cudaGetSymbolAddress(&xh, g_xh);
    cudaGetSymbolAddress(&xl, g_xl);

    // 1) split x into bf16 hi/lo
    split_kernel<<<2048, 256>>>(x, (__nv_bfloat16*)xh, (__nv_bfloat16*)xl,
                                (NROWS * DIN) / 4);

    // 2) fused recurrence + projection
    cudaFuncSetAttribute(fused_kernel,
                         cudaFuncAttributeMaxDynamicSharedMemorySize, FSMEM);
    fused_kernel<<<RBLOCKS, RTHREADS, FSMEM>>>(
        h0, w_ic, w_fc, b_ic, b_fc,
        w_cx, w_ix, w_fx, b_cx, b_ix, b_fx, out);
}

// round 13
// speedup vs baseline: 1.7640x; 1.7640x over previous
#include <cuda_runtime.h>
#include <cuda_bf16.h>
#include <math.h>
#include <stdint.h>

#define T_STEPS 512
#define BATCH   64
#define DH      1024
#define DIN     1024
#define NROWS   (T_STEPS * BATCH)        // 32768

// proj outputs (ctilde, ix, fx), each [T,B,H] f32.
__device__ float g_ct[(size_t)NROWS * DH];
__device__ float g_ix[(size_t)NROWS * DH];
__device__ float g_fx[(size_t)NROWS * DH];
__device__ unsigned g_bar;

// bf16 split scratch: x, proj weights, and per-step h
__device__ __nv_bfloat16 g_xh[(size_t)NROWS * DIN];
__device__ __nv_bfloat16 g_xl[(size_t)NROWS * DIN];
__device__ __nv_bfloat16 g_wh[(size_t)3 * DH * DIN];
__device__ __nv_bfloat16 g_wl[(size_t)3 * DH * DIN];
__device__ __nv_bfloat16 g_hh[(size_t)BATCH * DH];
__device__ __nv_bfloat16 g_hl[(size_t)BATCH * DH];

// ---------------------------------------------------------------------------
// Split kernel: fp32 -> (hi, lo) bf16 pair. (verified R10)
// ---------------------------------------------------------------------------
__global__ void __launch_bounds__(256) split_kernel(
    const float* __restrict__ src,
    __nv_bfloat16* __restrict__ hi, __nv_bfloat16* __restrict__ lo, int n4)
{
    for (int i = blockIdx.x * blockDim.x + threadIdx.x; i < n4;
         i += gridDim.x * blockDim.x) {
        const float4 v = ((const float4*)src)[i];
        const __nv_bfloat16 h0 = __float2bfloat16(v.x);
        const __nv_bfloat16 h1 = __float2bfloat16(v.y);
        const __nv_bfloat16 h2 = __float2bfloat16(v.z);
        const __nv_bfloat16 h3 = __float2bfloat16(v.w);
        const __nv_bfloat16 l0 = __float2bfloat16(v.x - __bfloat162float(h0));
        const __nv_bfloat16 l1 = __float2bfloat16(v.y - __bfloat162float(h1));
        const __nv_bfloat16 l2 = __float2bfloat16(v.z - __bfloat162float(h2));
        const __nv_bfloat16 l3 = __float2bfloat16(v.w - __bfloat162float(h3));
        __nv_bfloat162* H = (__nv_bfloat162*)hi;
        __nv_bfloat162* L = (__nv_bfloat162*)lo;
        H[2 * i]     = __halves2bfloat162(h0, h1);
        H[2 * i + 1] = __halves2bfloat162(h2, h3);
        L[2 * i]     = __halves2bfloat162(l0, l1);
        L[2 * i + 1] = __halves2bfloat162(l2, l3);
    }
}

__device__ __forceinline__ void mma_bf16(
    float& c0, float& c1, float& c2, float& c3,
    uint32_t a0, uint32_t a1, uint32_t a2, uint32_t a3,
    uint32_t b0, uint32_t b1)
{
    asm volatile(
        "mma.sync.aligned.m16n8k16.row.col.f32.bf16.bf16.f32 "
        "{%0,%1,%2,%3}, {%4,%5,%6,%7}, {%8,%9}, {%0,%1,%2,%3};"
        : "+f"(c0), "+f"(c1), "+f"(c2), "+f"(c3)
        : "r"(a0), "r"(a1), "r"(a2), "r"(a3), "r"(b0), "r"(b1));
}

// ---------------------------------------------------------------------------
// Tensor-core projection GEMM (verified R10, unchanged; ~93% of HMMA ceiling)
// ---------------------------------------------------------------------------
#define GSTR   40
#define SA_BUF (128 * GSTR)
#define SB_BUF (64 * GSTR)
#define GSMEM  ((2 * SA_BUF * 2 + 2 * SB_BUF * 2) * 2)

__global__ void __launch_bounds__(256, 2) gemm_kernel(
    const float* __restrict__ b_cx, const float* __restrict__ b_ix,
    const float* __restrict__ b_fx)
{
    extern __shared__ __nv_bfloat16 gsm[];
    __nv_bfloat16* sAh = gsm;
    __nv_bfloat16* sAl = gsm + 2 * SA_BUF;
    __nv_bfloat16* sBh = gsm + 4 * SA_BUF;
    __nv_bfloat16* sBl = gsm + 4 * SA_BUF + 2 * SB_BUF;

    const int tid   = threadIdx.x;
    const int lane  = tid & 31;
    const int warp  = tid >> 5;
    const int warpM = warp & 3;
    const int warpN = warp >> 2;
    const int g     = lane >> 2;
    const int tg    = lane & 3;

    const int mBase = blockIdx.y * 128;
    const int nGlob = blockIdx.x * 64;
    const int mat   = nGlob >> 10;
    const int nMat  = nGlob & 1023;

    const int lr = tid >> 2;
    const int lc = (tid & 3) * 8;
    const size_t aOff0 = (size_t)(mBase + lr) * DIN + lc;
    const size_t aOff1 = (size_t)(mBase + 64 + lr) * DIN + lc;
    const size_t bOff  = (size_t)(nGlob + lr) * DIN + lc;

    float acc[2][4][4];
#pragma unroll
    for (int mt = 0; mt < 2; mt++)
#pragma unroll
        for (int nt = 0; nt < 4; nt++)
#pragma unroll
            for (int q = 0; q < 4; q++) acc[mt][nt][q] = 0.f;

    uint4 rah0 = *(const uint4*)(g_xh + aOff0);
    uint4 rah1 = *(const uint4*)(g_xh + aOff1);
    uint4 ral0 = *(const uint4*)(g_xl + aOff0);
    uint4 ral1 = *(const uint4*)(g_xl + aOff1);
    uint4 rbh  = *(const uint4*)(g_wh + bOff);
    uint4 rbl  = *(const uint4*)(g_wl + bOff);
    {
        const int sa = lr * GSTR + lc;
        *(uint4*)(sAh + sa) = rah0;
        *(uint4*)(sAh + sa + 64 * GSTR) = rah1;
        *(uint4*)(sAl + sa) = ral0;
        *(uint4*)(sAl + sa + 64 * GSTR) = ral1;
        *(uint4*)(sBh + sa) = rbh;
        *(uint4*)(sBl + sa) = rbl;
    }
    __syncthreads();

    const int aRowOff0 = (warpM * 32 + g) * GSTR;
    const int bColOff  = (warpN * 32 + g) * GSTR;

#pragma unroll 1
    for (int s = 0; s < 32; s++) {
        const int cur = s & 1;
        const __nv_bfloat16* Ah = sAh + cur * SA_BUF;
        const __nv_bfloat16* Al = sAl + cur * SA_BUF;
        const __nv_bfloat16* Bh = sBh + cur * SB_BUF;
        const __nv_bfloat16* Bl = sBl + cur * SB_BUF;

        if (s < 31) {
            const int k0 = (s + 1) * 32;
            rah0 = *(const uint4*)(g_xh + aOff0 + k0);
            rah1 = *(const uint4*)(g_xh + aOff1 + k0);
            ral0 = *(const uint4*)(g_xl + aOff0 + k0);
            ral1 = *(const uint4*)(g_xl + aOff1 + k0);
            rbh  = *(const uint4*)(g_wh + bOff + k0);
            rbl  = *(const uint4*)(g_wl + bOff + k0);
        }

#pragma unroll
        for (int kk = 0; kk < 32; kk += 16) {
            uint32_t fah[2][4], fal[2][4], fbh[4][2], fbl[4][2];
#pragma unroll
            for (int mt = 0; mt < 2; mt++) {
                const int r = aRowOff0 + mt * 16 * GSTR + kk + tg * 2;
                fah[mt][0] = *(const uint32_t*)(Ah + r);
                fah[mt][1] = *(const uint32_t*)(Ah + r + 8 * GSTR);
                fah[mt][2] = *(const uint32_t*)(Ah + r + 8);
                fah[mt][3] = *(const uint32_t*)(Ah + r + 8 * GSTR + 8);
                fal[mt][0] = *(const uint32_t*)(Al + r);
                fal[mt][1] = *(const uint32_t*)(Al + r + 8 * GSTR);
                fal[mt][2] = *(const uint32_t*)(Al + r + 8);
                fal[mt][3] = *(const uint32_t*)(Al + r + 8 * GSTR + 8);
            }
#pragma unroll
            for (int nt = 0; nt < 4; nt++) {
                const int c = bColOff + nt * 8 * GSTR + kk + tg * 2;
                fbh[nt][0] = *(const uint32_t*)(Bh + c);
                fbh[nt][1] = *(const uint32_t*)(Bh + c + 8);
                fbl[nt][0] = *(const uint32_t*)(Bl + c);
                fbl[nt][1] = *(const uint32_t*)(Bl + c + 8);
            }
#pragma unroll
            for (int mt = 0; mt < 2; mt++)
#pragma unroll
                for (int nt = 0; nt < 4; nt++) {
                    mma_bf16(acc[mt][nt][0], acc[mt][nt][1],
                             acc[mt][nt][2], acc[mt][nt][3],
                             fah[mt][0], fah[mt][1], fah[mt][2], fah[mt][3],
                             fbh[nt][0], fbh[nt][1]);
                    mma_bf16(acc[mt][nt][0], acc[mt][nt][1],
                             acc[mt][nt][2], acc[mt][nt][3],
                             fah[mt][0], fah[mt][1], fah[mt][2], fah[mt][3],
                             fbl[nt][0], fbl[nt][1]);
                    mma_bf16(acc[mt][nt][0], acc[mt][nt][1],
                             acc[mt][nt][2], acc[mt][nt][3],
                             fal[mt][0], fal[mt][1], fal[mt][2], fal[mt][3],
                             fbh[nt][0], fbh[nt][1]);
                }
        }

        if (s < 31) {
            const int nxt = cur ^ 1;
            const int sa = lr * GSTR + lc;
            *(uint4*)(sAh + nxt * SA_BUF + sa) = rah0;
            *(uint4*)(sAh + nxt * SA_BUF + sa + 64 * GSTR) = rah1;
            *(uint4*)(sAl + nxt * SA_BUF + sa) = ral0;
            *(uint4*)(sAl + nxt * SA_BUF + sa + 64 * GSTR) = ral1;
            *(uint4*)(sBh + nxt * SB_BUF + sa) = rbh;
            *(uint4*)(sBl + nxt * SB_BUF + sa) = rbl;
            __syncthreads();
        }
    }

    float* dst = (mat == 0) ? g_ct : ((mat == 1) ? g_ix : g_fx);
    const float* bias = (mat == 0) ? b_cx : ((mat == 1) ? b_ix : b_fx);
#pragma unroll
    for (int mt = 0; mt < 2; mt++)
#pragma unroll
        for (int nt = 0; nt < 4; nt++) {
            const int col = nMat + warpN * 32 + nt * 8 + tg * 2;
            const float2 bb = *(const float2*)(bias + col);
            const int r0 = mBase + warpM * 32 + mt * 16 + g;
            float2 o0 = {acc[mt][nt][0] + bb.x, acc[mt][nt][1] + bb.y};
            float2 o1 = {acc[mt][nt][2] + bb.x, acc[mt][nt][3] + bb.y};
            *(float2*)(dst + (size_t)r0 * DH + col) = o0;
            *(float2*)(dst + (size_t)(r0 + 8) * DH + col) = o1;
        }
}

// ---------------------------------------------------------------------------
// HMMA recurrence: per block per step GEMM M=64, N=16 (8 cols x 2 gates),
// K=1024, bf16 split-3 on the tensor pipe (FFMA and HMMA proven non-
// overlapping; HMMA is 4x the MAC rate). h re-split to bf16 hi/lo each step.
// 128 blocks x 512 threads; warp w: kc2=w>>3 (k half), ntk=(w>>2)&1 (gate),
// mt=w&3 (m16 tile). 12 mma/warp/stage, 8 stages of 128 k.
// ---------------------------------------------------------------------------
#define RBLOCKS   128
#define RTHREADS  512
#define HC_STR    136                      // bf16 elems per h-chunk row
#define HC_ELEM   (64 * HC_STR)            // 8704
#define WB_STR    1032
// smem byte offsets
#define OFF_WBH   0                        // [16][1032] bf16 = 33024
#define OFF_WBL   33024
#define OFF_HSH   66048                    // 2 x [64][136] bf16 = 34816
#define OFF_HSL   100864
#define OFF_SCR   135680                   // 8*32*5 f32 = 5120
#define OFF_PB    140800                   // [64][18] f32 = 4608
#define MSMEM     145408

__global__ void __launch_bounds__(RTHREADS) recur_mma_kernel(
    const float* __restrict__ h0,
    const float* __restrict__ w_ic, const float* __restrict__ w_fc,
    const float* __restrict__ b_ic, const float* __restrict__ b_fc,
    float* __restrict__ out)
{
    extern __shared__ __align__(16) char smc[];
    __nv_bfloat16* wbh = (__nv_bfloat16*)(smc + OFF_WBH);
    __nv_bfloat16* wbl = (__nv_bfloat16*)(smc + OFF_WBL);
    __nv_bfloat16* hsh = (__nv_bfloat16*)(smc + OFF_HSH);
    __nv_bfloat16* hsl = (__nv_bfloat16*)(smc + OFF_HSL);
    float* scr = (float*)(smc + OFF_SCR);
    float* pbf = (float*)(smc + OFF_PB);

    const int tid  = threadIdx.x;
    const int wid  = tid >> 5;
    const int lane = tid & 31;
    const int g    = lane >> 2;
    const int tg   = lane & 3;
    const int mt   = wid & 3;
    const int ntk  = (wid >> 2) & 1;
    const int kc2  = wid >> 3;
    const int jb   = blockIdx.x;

    // epilogue element: one per thread
    const int erow = tid >> 3;             // 0..63
    const int ecol = tid & 7;              // 0..7
    const int colg = jb * 8 + ecol;
    const float bi = b_ic[colg];
    const float bf = b_fc[colg];

    // ---- load + split gate weights to smem bf16 hi/lo: n = gate*8 + r ----
    for (int i = tid; i < 16 * 256; i += RTHREADS) {
        const int n = i >> 8;
        const int o = (i & 255) * 4;
        const float* ws = (n < 8 ? w_ic + (size_t)(jb * 8 + n) * DH
                                 : w_fc + (size_t)(jb * 8 + n - 8) * DH) + o;
        const float4 v = *(const float4*)ws;
        const float vv[4] = {v.x, v.y, v.z, v.w};
        __nv_bfloat16* dh = wbh + n * WB_STR + o;
        __nv_bfloat16* dl = wbl + n * WB_STR + o;
#pragma unroll
        for (int q = 0; q < 4; q++) {
            const __nv_bfloat16 h = __float2bfloat16(vv[q]);
            dh[q] = h;
            dl[q] = __float2bfloat16(vv[q] - __bfloat162float(h));
        }
    }

    // ---- prologue: convert this block's h0 cols to g_hh/g_hl ----
    {
        const float v = h0[(size_t)erow * DH + colg];
        const __nv_bfloat16 h = __float2bfloat16(v);
        g_hh[(size_t)erow * DH + colg] = h;
        g_hl[(size_t)erow * DH + colg] = __float2bfloat16(v - __bfloat162float(h));
    }
    const unsigned nb = gridDim.x;
    __threadfence();
    __syncthreads();
    if (tid == 0) {
        atomicAdd(&g_bar, 1u);
        while (*((volatile unsigned*)&g_bar) < nb) { }
        __threadfence();
    }
    __syncthreads();

    // fill mapping: 2 uint4 per thread per stage (hi and lo each)
    const int frow = tid >> 4;             // 0..31 (u=0); +32 for u=1
    const int fkq  = (tid & 15) * 8;       // bf16 offset within 128-k chunk

    const float* hprev = h0;

#pragma unroll 1
    for (int t = 0; t < T_STEPS; t++) {
        const size_t ob = (size_t)t * (BATCH * DH);

        // prefetch epilogue operands (DRAM latency hidden under mainloop)
        const size_t ebase = ob + (size_t)erow * DH + colg;
        const float e_ix = g_ix[ebase];
        const float e_fx = g_fx[ebase];
        const float e_ct = g_ct[ebase];
        const float e_hp = hprev[(size_t)erow * DH + colg];

        float acc0 = 0.f, acc1 = 0.f, acc2 = 0.f, acc3 = 0.f;

        // stage 0 fill
        uint4 ph0 = *(const uint4*)(g_hh + (size_t)frow * DH + fkq);
        uint4 ph1 = *(const uint4*)(g_hh + (size_t)(frow + 32) * DH + fkq);
        uint4 pl0 = *(const uint4*)(g_hl + (size_t)frow * DH + fkq);
        uint4 pl1 = *(const uint4*)(g_hl + (size_t)(frow + 32) * DH + fkq);
        *(uint4*)(hsh + frow * HC_STR + fkq) = ph0;
        *(uint4*)(hsh + (frow + 32) * HC_STR + fkq) = ph1;
        *(uint4*)(hsl + frow * HC_STR + fkq) = pl0;
        *(uint4*)(hsl + (frow + 32) * HC_STR + fkq) = pl1;
        __syncthreads();

#pragma unroll 1
        for (int s = 0; s < 8; s++) {
            const int cb = (s & 1) * HC_ELEM;
            if (s < 7) {   // prefetch next chunk
                const int kn = (s + 1) * 128 + fkq;
                ph0 = *(const uint4*)(g_hh + (size_t)frow * DH + kn);
                ph1 = *(const uint4*)(g_hh + (size_t)(frow + 32) * DH + kn);
                pl0 = *(const uint4*)(g_hl + (size_t)frow * DH + kn);
                pl1 = *(const uint4*)(g_hl + (size_t)(frow + 32) * DH + kn);
            }

            const int kb = kc2 * 64;       // k offset within chunk
            const int kw = s * 128 + kc2 * 64;  // k offset for weights
            const int ar = (mt * 16 + g) * HC_STR;
            const int br = (ntk * 8 + g) * WB_STR;
#pragma unroll
            for (int k4 = 0; k4 < 4; k4++) {
                const int ko = kb + k4 * 16 + tg * 2;
                const int kwo = kw + k4 * 16 + tg * 2;
                const uint32_t ah0 = *(const uint32_t*)(hsh + cb + ar + ko);
                const uint32_t ah1 = *(const uint32_t*)(hsh + cb + ar + 8 * HC_STR + ko);
                const uint32_t ah2 = *(const uint32_t*)(hsh + cb + ar + ko + 8);
                const uint32_t ah3 = *(const uint32_t*)(hsh + cb + ar + 8 * HC_STR + ko + 8);
                const uint32_t al0 = *(const uint32_t*)(hsl + cb + ar + ko);
                const uint32_t al1 = *(const uint32_t*)(hsl + cb + ar + 8 * HC_STR + ko);
                const uint32_t al2 = *(const uint32_t*)(hsl + cb + ar + ko + 8);
                const uint32_t al3 = *(const uint32_t*)(hsl + cb + ar + 8 * HC_STR + ko + 8);
                const uint32_t bh0 = *(const uint32_t*)(wbh + br + kwo);
                const uint32_t bh1 = *(const uint32_t*)(wbh + br + kwo + 8);
                const uint32_t bl0 = *(const uint32_t*)(wbl + br + kwo);
                const uint32_t bl1 = *(const uint32_t*)(wbl + br + kwo + 8);
                mma_bf16(acc0, acc1, acc2, acc3, ah0, ah1, ah2, ah3, bh0, bh1);
                mma_bf16(acc0, acc1, acc2, acc3, ah0, ah1, ah2, ah3, bl0, bl1);
                mma_bf16(acc0, acc1, acc2, acc3, al0, al1, al2, al3, bh0, bh1);
            }

            if (s < 7) {   // store next chunk to other buffer, one sync
                const int nb2 = ((s + 1) & 1) * HC_ELEM;
                *(uint4*)(hsh + nb2 + frow * HC_STR + fkq) = ph0;
                *(uint4*)(hsh + nb2 + (frow + 32) * HC_STR + fkq) = ph1;
                *(uint4*)(hsl + nb2 + frow * HC_STR + fkq) = pl0;
                *(uint4*)(hsl + nb2 + (frow + 32) * HC_STR + fkq) = pl1;
                __syncthreads();
            }
        }

        // ---- kc2 reduction (warps 8-15 -> scr, warps 0-7 add) ----
        __syncthreads();
        if (kc2 == 1) {
            const int slot = ((wid - 8) * 32 + lane) * 5;
            scr[slot + 0] = acc0; scr[slot + 1] = acc1;
            scr[slot + 2] = acc2; scr[slot + 3] = acc3;
        }
        __syncthreads();
        if (kc2 == 0) {
            const int slot = (wid * 32 + lane) * 5;
            acc0 += scr[slot + 0]; acc1 += scr[slot + 1];
            acc2 += scr[slot + 2]; acc3 += scr[slot + 3];
            // write pre-activations to pbuf [64][18]
            const int r0 = mt * 16 + g;
            const int cc = ntk * 8 + tg * 2;
            *(float2*)(pbf + r0 * 18 + cc) = make_float2(acc0, acc1);
            *(float2*)(pbf + (r0 + 8) * 18 + cc) = make_float2(acc2, acc3);
        }
        __syncthreads();

        // ---- per-thread epilogue: one (row, col) element ----
        {
            const float pi = pbf[erow * 18 + ecol] + bi + e_ix;
            const float pv = pbf[erow * 18 + ecol + 8] + bf + e_fx;
            const float ig = 1.f / (1.f + expf(-pi));
            const float fg = 1.f / (1.f + expf(-pv));
            const float cc = ig * e_ct + fg * e_hp;
            const float hn = tanhf(cc);
            out[ebase] = hn;
            if (t == T_STEPS - 1) {
                out[(size_t)T_STEPS * BATCH * DH + (size_t)erow * DH + colg] = hn;
            }
            const __nv_bfloat16 hh = __float2bfloat16(hn);
            g_hh[(size_t)erow * DH + colg] = hh;
            g_hl[(size_t)erow * DH + colg] =
                __float2bfloat16(hn - __bfloat162float(hh));
        }

        // ---- grid-wide barrier ----
        __threadfence();
        __syncthreads();
        if (tid == 0) {
            atomicAdd(&g_bar, 1u);
            const unsigned target = (unsigned)(t + 2) * nb;
            while (*((volatile unsigned*)&g_bar) < target) { }
            __threadfence();
        }
        __syncthreads();

        hprev = out + ob;
    }
}

// ---------------------------------------------------------------------------
extern "C" void kernel_launch(void* const* d_in, const int* in_sizes, int n_in,
                              void* d_out, int out_size)
{
    const float* x    = (const float*)d_in[0];
    const float* h0   = (const float*)d_in[1];
    const float* w_cx = (const float*)d_in[2];
    const float* w_ic = (const float*)d_in[3];
    const float* w_ix = (const float*)d_in[4];
    const float* w_fc = (const float*)d_in[5];
    const float* w_fx = (const float*)d_in[6];
    const float* b_cx = (const float*)d_in[7];
    const float* b_ic = (const float*)d_in[8];
    const float* b_ix = (const float*)d_in[9];
    const float* b_fc = (const float*)d_in[10];
    const float* b_fx = (const float*)d_in[11];
    float* out = (float*)d_out;

    // reset grid-barrier counter
    void* barAddr = nullptr;
    cudaGetSymbolAddress(&barAddr, g_bar);
    cudaMemsetAsync(barAddr, 0, sizeof(unsigned), 0);

    void *xh, *xl, *wh, *wl;
    cudaGetSymbolAddress(&xh, g_xh);
    cudaGetSymbolAddress(&xl, g_xl);
    cudaGetSymbolAddress(&wh, g_wh);
    cudaGetSymbolAddress(&wl, g_wl);

    // 1) split x and proj weights into bf16 hi/lo
    split_kernel<<<2048, 256>>>(x, (__nv_bfloat16*)xh, (__nv_bfloat16*)xl,
                                (NROWS * DIN) / 4);
    const int wn4 = (DH * DIN) / 4;
    split_kernel<<<512, 256>>>(w_cx, (__nv_bfloat16*)wh, (__nv_bfloat16*)wl, wn4);
    split_kernel<<<512, 256>>>(w_ix, (__nv_bfloat16*)wh + (size_t)DH * DIN,
                               (__nv_bfloat16*)wl + (size_t)DH * DIN, wn4);
    split_kernel<<<512, 256>>>(w_fx, (__nv_bfloat16*)wh + (size_t)2 * DH * DIN,
                               (__nv_bfloat16*)wl + (size_t)2 * DH * DIN, wn4);

    // 2) tensor-core projection GEMM
    cudaFuncSetAttribute(gemm_kernel,
                         cudaFuncAttributeMaxDynamicSharedMemorySize, GSMEM);
    dim3 ggrid(3 * DH / 64, NROWS / 128);
    gemm_kernel<<<ggrid, 256, GSMEM>>>(b_cx, b_ix, b_fx);

    // 3) HMMA persistent recurrence
    cudaFuncSetAttribute(recur_mma_kernel,
                         cudaFuncAttributeMaxDynamicSharedMemorySize, MSMEM);
    recur_mma_kernel<<<RBLOCKS, RTHREADS, MSMEM>>>(h0, w_ic, w_fc, b_ic, b_fc, out);
}

// round 14
// speedup vs baseline: 2.0936x; 1.1869x over previous
#include <cuda_runtime.h>
#include <cuda_fp16.h>
#include <math.h>
#include <stdint.h>

#define T_STEPS 512
#define BATCH   64
#define DH      1024
#define DIN     1024
#define NROWS   (T_STEPS * BATCH)        // 32768

// proj outputs (ctilde, ix, fx), each [T,B,H] f32.
__device__ float g_ct[(size_t)NROWS * DH];
__device__ float g_ix[(size_t)NROWS * DH];
__device__ float g_fx[(size_t)NROWS * DH];
__device__ unsigned g_bar;

// fp16 scratch: x (rounded once), proj weights (hi/lo split), per-step h
__device__ __half g_xh[(size_t)NROWS * DIN];
__device__ __half g_wh[(size_t)3 * DH * DIN];
__device__ __half g_wl[(size_t)3 * DH * DIN];
__device__ __half g_hh[(size_t)BATCH * DH];

// ---------------------------------------------------------------------------
// Convert kernel: fp32 -> fp16 (round once; error 2^-12 rms relative)
// ---------------------------------------------------------------------------
__global__ void __launch_bounds__(256) cvt_half_kernel(
    const float* __restrict__ src, __half* __restrict__ dst, int n4)
{
    for (int i = blockIdx.x * blockDim.x + threadIdx.x; i < n4;
         i += gridDim.x * blockDim.x) {
        const float4 v = ((const float4*)src)[i];
        __half2* D = (__half2*)dst;
        D[2 * i]     = __halves2half2(__float2half(v.x), __float2half(v.y));
        D[2 * i + 1] = __halves2half2(__float2half(v.z), __float2half(v.w));
    }
}

// Split kernel: fp32 -> (hi, lo) fp16 pair.  a = hi + lo + O(2^-22 |a|)
__global__ void __launch_bounds__(256) split_half_kernel(
    const float* __restrict__ src,
    __half* __restrict__ hi, __half* __restrict__ lo, int n4)
{
    for (int i = blockIdx.x * blockDim.x + threadIdx.x; i < n4;
         i += gridDim.x * blockDim.x) {
        const float4 v = ((const float4*)src)[i];
        const float vv[4] = {v.x, v.y, v.z, v.w};
        __half h[4], l[4];
#pragma unroll
        for (int q = 0; q < 4; q++) {
            h[q] = __float2half(vv[q]);
            l[q] = __float2half(vv[q] - __half2float(h[q]));
        }
        __half2* H = (__half2*)hi;
        __half2* L = (__half2*)lo;
        H[2 * i]     = __halves2half2(h[0], h[1]);
        H[2 * i + 1] = __halves2half2(h[2], h[3]);
        L[2 * i]     = __halves2half2(l[0], l[1]);
        L[2 * i + 1] = __halves2half2(l[2], l[3]);
    }
}

__device__ __forceinline__ void mma_f16(
    float& c0, float& c1, float& c2, float& c3,
    uint32_t a0, uint32_t a1, uint32_t a2, uint32_t a3,
    uint32_t b0, uint32_t b1)
{
    asm volatile(
        "mma.sync.aligned.m16n8k16.row.col.f32.f16.f16.f32 "
        "{%0,%1,%2,%3}, {%4,%5,%6,%7}, {%8,%9}, {%0,%1,%2,%3};"
        : "+f"(c0), "+f"(c1), "+f"(c2), "+f"(c3)
        : "r"(a0), "r"(a1), "r"(a2), "r"(a3), "r"(b0), "r"(b1));
}

// ---------------------------------------------------------------------------
// Projection GEMM: C[m][n] = sum_k x[m][k] * Wcat[n][k] (+bias)
// fp16 split-2: A (x) rounded once; W split hi/lo. 2 mma passes:
//   Ah*Wh + Ah*Wl  (= Ah*W exactly; only error is x-rounding ~2^-12)
// Tile/fragments identical to the R10-verified layout.
// ---------------------------------------------------------------------------
#define GSTR   40
#define SA_BUF (128 * GSTR)
#define SB_BUF (64 * GSTR)
#define GSMEM  ((2 * SA_BUF + 2 * SB_BUF * 2) * 2)   // 40960 bytes

__global__ void __launch_bounds__(256, 2) gemm_kernel(
    const float* __restrict__ b_cx, const float* __restrict__ b_ix,
    const float* __restrict__ b_fx)
{
    extern __shared__ __half gsm[];
    __half* sAh = gsm;                          // [2][SA_BUF]
    __half* sBh = gsm + 2 * SA_BUF;             // [2][SB_BUF]
    __half* sBl = gsm + 2 * SA_BUF + 2 * SB_BUF;

    const int tid   = threadIdx.x;
    const int lane  = tid & 31;
    const int warp  = tid >> 5;
    const int warpM = warp & 3;
    const int warpN = warp >> 2;
    const int g     = lane >> 2;
    const int tg    = lane & 3;

    const int mBase = blockIdx.y * 128;
    const int nGlob = blockIdx.x * 64;
    const int mat   = nGlob >> 10;
    const int nMat  = nGlob & 1023;

    const int lr = tid >> 2;
    const int lc = (tid & 3) * 8;
    const size_t aOff0 = (size_t)(mBase + lr) * DIN + lc;
    const size_t aOff1 = (size_t)(mBase + 64 + lr) * DIN + lc;
    const size_t bOff  = (size_t)(nGlob + lr) * DIN + lc;

    float acc[2][4][4];
#pragma unroll
    for (int mt = 0; mt < 2; mt++)
#pragma unroll
        for (int nt = 0; nt < 4; nt++)
#pragma unroll
            for (int q = 0; q < 4; q++) acc[mt][nt][q] = 0.f;

    uint4 rah0 = *(const uint4*)(g_xh + aOff0);
    uint4 rah1 = *(const uint4*)(g_xh + aOff1);
    uint4 rbh  = *(const uint4*)(g_wh + bOff);
    uint4 rbl  = *(const uint4*)(g_wl + bOff);
    {
        const int sa = lr * GSTR + lc;
        *(uint4*)(sAh + sa) = rah0;
        *(uint4*)(sAh + sa + 64 * GSTR) = rah1;
        *(uint4*)(sBh + sa) = rbh;
        *(uint4*)(sBl + sa) = rbl;
    }
    __syncthreads();

    const int aRowOff0 = (warpM * 32 + g) * GSTR;
    const int bColOff  = (warpN * 32 + g) * GSTR;

#pragma unroll 1
    for (int s = 0; s < 32; s++) {
        const int cur = s & 1;
        const __half* Ah = sAh + cur * SA_BUF;
        const __half* Bh = sBh + cur * SB_BUF;
        const __half* Bl = sBl + cur * SB_BUF;

        if (s < 31) {
            const int k0 = (s + 1) * 32;
            rah0 = *(const uint4*)(g_xh + aOff0 + k0);
            rah1 = *(const uint4*)(g_xh + aOff1 + k0);
            rbh  = *(const uint4*)(g_wh + bOff + k0);
            rbl  = *(const uint4*)(g_wl + bOff + k0);
        }

#pragma unroll
        for (int kk = 0; kk < 32; kk += 16) {
            uint32_t fah[2][4], fbh[4][2], fbl[4][2];
#pragma unroll
            for (int mt = 0; mt < 2; mt++) {
                const int r = aRowOff0 + mt * 16 * GSTR + kk + tg * 2;
                fah[mt][0] = *(const uint32_t*)(Ah + r);
                fah[mt][1] = *(const uint32_t*)(Ah + r + 8 * GSTR);
                fah[mt][2] = *(const uint32_t*)(Ah + r + 8);
                fah[mt][3] = *(const uint32_t*)(Ah + r + 8 * GSTR + 8);
            }
#pragma unroll
            for (int nt = 0; nt < 4; nt++) {
                const int c = bColOff + nt * 8 * GSTR + kk + tg * 2;
                fbh[nt][0] = *(const uint32_t*)(Bh + c);
                fbh[nt][1] = *(const uint32_t*)(Bh + c + 8);
                fbl[nt][0] = *(const uint32_t*)(Bl + c);
                fbl[nt][1] = *(const uint32_t*)(Bl + c + 8);
            }
#pragma unroll
            for (int mt = 0; mt < 2; mt++)
#pragma unroll
                for (int nt = 0; nt < 4; nt++) {
                    mma_f16(acc[mt][nt][0], acc[mt][nt][1],
                            acc[mt][nt][2], acc[mt][nt][3],
                            fah[mt][0], fah[mt][1], fah[mt][2], fah[mt][3],
                            fbh[nt][0], fbh[nt][1]);
                    mma_f16(acc[mt][nt][0], acc[mt][nt][1],
                            acc[mt][nt][2], acc[mt][nt][3],
                            fah[mt][0], fah[mt][1], fah[mt][2], fah[mt][3],
                            fbl[nt][0], fbl[nt][1]);
                }
        }

        if (s < 31) {
            const int nxt = cur ^ 1;
            const int sa = lr * GSTR + lc;
            *(uint4*)(sAh + nxt * SA_BUF + sa) = rah0;
            *(uint4*)(sAh + nxt * SA_BUF + sa + 64 * GSTR) = rah1;
            *(uint4*)(sBh + nxt * SB_BUF + sa) = rbh;
            *(uint4*)(sBl + nxt * SB_BUF + sa) = rbl;
            __syncthreads();
        }
    }

    float* dst = (mat == 0) ? g_ct : ((mat == 1) ? g_ix : g_fx);
    const float* bias = (mat == 0) ? b_cx : ((mat == 1) ? b_ix : b_fx);
#pragma unroll
    for (int mt = 0; mt < 2; mt++)
#pragma unroll
        for (int nt = 0; nt < 4; nt++) {
            const int col = nMat + warpN * 32 + nt * 8 + tg * 2;
            const float2 bb = *(const float2*)(bias + col);
            const int r0 = mBase + warpM * 32 + mt * 16 + g;
            float2 o0 = {acc[mt][nt][0] + bb.x, acc[mt][nt][1] + bb.y};
            float2 o1 = {acc[mt][nt][2] + bb.x, acc[mt][nt][3] + bb.y};
            *(float2*)(dst + (size_t)r0 * DH + col) = o0;
            *(float2*)(dst + (size_t)(r0 + 8) * DH + col) = o1;
        }
}

// ---------------------------------------------------------------------------
// HMMA recurrence (R13-verified structure), fp16 split-2:
// h rounded to fp16 each step; gate weights split hi/lo in smem.
// 8 mma/warp/stage (was 12). Per block per step: 2.1M issued MAC = 8.2K cyc.
// ---------------------------------------------------------------------------
#define RBLOCKS   128
#define RTHREADS  512
#define HC_STR    136
#define HC_ELEM   (64 * HC_STR)
#define WB_STR    1032
// smem byte offsets (fp16 = 2B)
#define OFF_WBH   0                        // [16][1032] = 33024
#define OFF_WBL   33024
#define OFF_HSH   66048                    // 2 x [64][136] = 34816
#define OFF_SCR   100864                   // 8*32*5 f32 = 5120
#define OFF_PB    105984                   // [64][18] f32 = 4608
#define MSMEM     110592

__global__ void __launch_bounds__(RTHREADS) recur_mma_kernel(
    const float* __restrict__ h0,
    const float* __restrict__ w_ic, const float* __restrict__ w_fc,
    const float* __restrict__ b_ic, const float* __restrict__ b_fc,
    float* __restrict__ out)
{
    extern __shared__ __align__(16) char smc[];
    __half* wbh = (__half*)(smc + OFF_WBH);
    __half* wbl = (__half*)(smc + OFF_WBL);
    __half* hsh = (__half*)(smc + OFF_HSH);
    float* scr = (float*)(smc + OFF_SCR);
    float* pbf = (float*)(smc + OFF_PB);

    const int tid  = threadIdx.x;
    const int wid  = tid >> 5;
    const int lane = tid & 31;
    const int g    = lane >> 2;
    const int tg   = lane & 3;
    const int mt   = wid & 3;
    const int ntk  = (wid >> 2) & 1;
    const int kc2  = wid >> 3;
    const int jb   = blockIdx.x;

    const int erow = tid >> 3;
    const int ecol = tid & 7;
    const int colg = jb * 8 + ecol;
    const float bi = b_ic[colg];
    const float bf = b_fc[colg];

    // ---- load + split gate weights to smem fp16 hi/lo: n = gate*8 + r ----
    for (int i = tid; i < 16 * 256; i += RTHREADS) {
        const int n = i >> 8;
        const int o = (i & 255) * 4;
        const float* ws = (n < 8 ? w_ic + (size_t)(jb * 8 + n) * DH
                                 : w_fc + (size_t)(jb * 8 + n - 8) * DH) + o;
        const float4 v = *(const float4*)ws;
        const float vv[4] = {v.x, v.y, v.z, v.w};
        __half* dh = wbh + n * WB_STR + o;
        __half* dl = wbl + n * WB_STR + o;
#pragma unroll
        for (int q = 0; q < 4; q++) {
            const __half h = __float2half(vv[q]);
            dh[q] = h;
            dl[q] = __float2half(vv[q] - __half2float(h));
        }
    }

    // ---- prologue: convert this block's h0 cols to fp16 ----
    {
        const float v = h0[(size_t)erow * DH + colg];
        g_hh[(size_t)erow * DH + colg] = __float2half(v);
    }
    const unsigned nb = gridDim.x;
    __threadfence();
    __syncthreads();
    if (tid == 0) {
        atomicAdd(&g_bar, 1u);
        while (*((volatile unsigned*)&g_bar) < nb) { }
        __threadfence();
    }
    __syncthreads();

    const int frow = tid >> 4;             // 0..31 (+32 for second half)
    const int fkq  = (tid & 15) * 8;

    const float* hprev = h0;

#pragma unroll 1
    for (int t = 0; t < T_STEPS; t++) {
        const size_t ob = (size_t)t * (BATCH * DH);

        const size_t ebase = ob + (size_t)erow * DH + colg;
        const float e_ix = g_ix[ebase];
        const float e_fx = g_fx[ebase];
        const float e_ct = g_ct[ebase];
        const float e_hp = hprev[(size_t)erow * DH + colg];

        float acc0 = 0.f, acc1 = 0.f, acc2 = 0.f, acc3 = 0.f;

        uint4 ph0 = *(const uint4*)(g_hh + (size_t)frow * DH + fkq);
        uint4 ph1 = *(const uint4*)(g_hh + (size_t)(frow + 32) * DH + fkq);
        *(uint4*)(hsh + frow * HC_STR + fkq) = ph0;
        *(uint4*)(hsh + (frow + 32) * HC_STR + fkq) = ph1;
        __syncthreads();

#pragma unroll 1
        for (int s = 0; s < 8; s++) {
            const int cb = (s & 1) * HC_ELEM;
            if (s < 7) {
                const int kn = (s + 1) * 128 + fkq;
                ph0 = *(const uint4*)(g_hh + (size_t)frow * DH + kn);
                ph1 = *(const uint4*)(g_hh + (size_t)(frow + 32) * DH + kn);
            }

            const int kb = kc2 * 64;
            const int kw = s * 128 + kc2 * 64;
            const int ar = (mt * 16 + g) * HC_STR;
            const int br = (ntk * 8 + g) * WB_STR;
#pragma unroll
            for (int k4 = 0; k4 < 4; k4++) {
                const int ko = kb + k4 * 16 + tg * 2;
                const int kwo = kw + k4 * 16 + tg * 2;
                const uint32_t ah0 = *(const uint32_t*)(hsh + cb + ar + ko);
                const uint32_t ah1 = *(const uint32_t*)(hsh + cb + ar + 8 * HC_STR + ko);
                const uint32_t ah2 = *(const uint32_t*)(hsh + cb + ar + ko + 8);
                const uint32_t ah3 = *(const uint32_t*)(hsh + cb + ar + 8 * HC_STR + ko + 8);
                const uint32_t bh0 = *(const uint32_t*)(wbh + br + kwo);
                const uint32_t bh1 = *(const uint32_t*)(wbh + br + kwo + 8);
                const uint32_t bl0 = *(const uint32_t*)(wbl + br + kwo);
                const uint32_t bl1 = *(const uint32_t*)(wbl + br + kwo + 8);
                mma_f16(acc0, acc1, acc2, acc3, ah0, ah1, ah2, ah3, bh0, bh1);
                mma_f16(acc0, acc1, acc2, acc3, ah0, ah1, ah2, ah3, bl0, bl1);
            }

            if (s < 7) {
                const int nb2 = ((s + 1) & 1) * HC_ELEM;
                *(uint4*)(hsh + nb2 + frow * HC_STR + fkq) = ph0;
                *(uint4*)(hsh + nb2 + (frow + 32) * HC_STR + fkq) = ph1;
                __syncthreads();
            }
        }

        // ---- kc2 reduction ----
        __syncthreads();
        if (kc2 == 1) {
            const int slot = ((wid - 8) * 32 + lane) * 5;
            scr[slot + 0] = acc0; scr[slot + 1] = acc1;
            scr[slot + 2] = acc2; scr[slot + 3] = acc3;
        }
        __syncthreads();
        if (kc2 == 0) {
            const int slot = (wid * 32 + lane) * 5;
            acc0 += scr[slot + 0]; acc1 += scr[slot + 1];
            acc2 += scr[slot + 2]; acc3 += scr[slot + 3];
            const int r0 = mt * 16 + g;
            const int cc = ntk * 8 + tg * 2;
            *(float2*)(pbf + r0 * 18 + cc) = make_float2(acc0, acc1);
            *(float2*)(pbf + (r0 + 8) * 18 + cc) = make_float2(acc2, acc3);
        }
        __syncthreads();

        // ---- per-thread epilogue ----
        {
            const float pi = pbf[erow * 18 + ecol] + bi + e_ix;
            const float pv = pbf[erow * 18 + ecol + 8] + bf + e_fx;
            const float ig = 1.f / (1.f + expf(-pi));
            const float fg = 1.f / (1.f + expf(-pv));
            const float cc = ig * e_ct + fg * e_hp;
            const float hn = tanhf(cc);
            out[ebase] = hn;
            if (t == T_STEPS - 1) {
                out[(size_t)T_STEPS * BATCH * DH + (size_t)erow * DH + colg] = hn;
            }
            g_hh[(size_t)erow * DH + colg] = __float2half(hn);
        }

        // ---- grid-wide barrier ----
        __threadfence();
        __syncthreads();
        if (tid == 0) {
            atomicAdd(&g_bar, 1u);
            const unsigned target = (unsigned)(t + 2) * nb;
            while (*((volatile unsigned*)&g_bar) < target) { }
            __threadfence();
        }
        __syncthreads();

        hprev = out + ob;
    }
}

// ---------------------------------------------------------------------------
extern "C" void kernel_launch(void* const* d_in, const int* in_sizes, int n_in,
                              void* d_out, int out_size)
{
    const float* x    = (const float*)d_in[0];
    const float* h0   = (const float*)d_in[1];
    const float* w_cx = (const float*)d_in[2];
    const float* w_ic = (const float*)d_in[3];
    const float* w_ix = (const float*)d_in[4];
    const float* w_fc = (const float*)d_in[5];
    const float* w_fx = (const float*)d_in[6];
    const float* b_cx = (const float*)d_in[7];
    const float* b_ic = (const float*)d_in[8];
    const float* b_ix = (const float*)d_in[9];
    const float* b_fc = (const float*)d_in[10];
    const float* b_fx = (const float*)d_in[11];
    float* out = (float*)d_out;

    // reset grid-barrier counter
    void* barAddr = nullptr;
    cudaGetSymbolAddress(&barAddr, g_bar);
    cudaMemsetAsync(barAddr, 0, sizeof(unsigned), 0);

    void *xh, *wh, *wl;
    cudaGetSymbolAddress(&xh, g_xh);
    cudaGetSymbolAddress(&wh, g_wh);
    cudaGetSymbolAddress(&wl, g_wl);

    // 1) x -> fp16 (round once); weights -> fp16 hi/lo
    cvt_half_kernel<<<2048, 256>>>(x, (__half*)xh, (NROWS * DIN) / 4);
    const int wn4 = (DH * DIN) / 4;
    split_half_kernel<<<512, 256>>>(w_cx, (__half*)wh, (__half*)wl, wn4);
    split_half_kernel<<<512, 256>>>(w_ix, (__half*)wh + (size_t)DH * DIN,
                                    (__half*)wl + (size_t)DH * DIN, wn4);
    split_half_kernel<<<512, 256>>>(w_fx, (__half*)wh + (size_t)2 * DH * DIN,
                                    (__half*)wl + (size_t)2 * DH * DIN, wn4);

    // 2) fp16 split-2 projection GEMM
    cudaFuncSetAttribute(gemm_kernel,
                         cudaFuncAttributeMaxDynamicSharedMemorySize, GSMEM);
    dim3 ggrid(3 * DH / 64, NROWS / 128);
    gemm_kernel<<<ggrid, 256, GSMEM>>>(b_cx, b_ix, b_fx);

    // 3) fp16 split-2 HMMA persistent recurrence
    cudaFuncSetAttribute(recur_mma_kernel,
                         cudaFuncAttributeMaxDynamicSharedMemorySize, MSMEM);
    recur_mma_kernel<<<RBLOCKS, RTHREADS, MSMEM>>>(h0, w_ic, w_fc, b_ic, b_fc, out);
}

// round 16
// speedup vs baseline: 2.1013x; 1.0037x over previous
#include <cuda_runtime.h>
#include <cuda_fp16.h>
#include <math.h>
#include <stdint.h>

#define T_STEPS 512
#define BATCH   64
#define DH      1024
#define DIN     1024
#define NROWS   (T_STEPS * BATCH)        // 32768

// proj outputs (ctilde, ix, fx), each [T,B,H] f32.
__device__ float g_ct[(size_t)NROWS * DH];
__device__ float g_ix[(size_t)NROWS * DH];
__device__ float g_fx[(size_t)NROWS * DH];
__device__ unsigned g_bar;

// fp16 scratch: x (rounded once), proj weights (hi/lo split), per-step h
__device__ __half g_xh[(size_t)NROWS * DIN];
__device__ __half g_wh[(size_t)3 * DH * DIN];
__device__ __half g_wl[(size_t)3 * DH * DIN];
__device__ __half g_hh[(size_t)BATCH * DH];

// ---------------------------------------------------------------------------
// Convert kernel: fp32 -> fp16 (round once; error 2^-12 rms relative)
// ---------------------------------------------------------------------------
__global__ void __launch_bounds__(256) cvt_half_kernel(
    const float* __restrict__ src, __half* __restrict__ dst, int n4)
{
    for (int i = blockIdx.x * blockDim.x + threadIdx.x; i < n4;
         i += gridDim.x * blockDim.x) {
        const float4 v = ((const float4*)src)[i];
        __half2* D = (__half2*)dst;
        D[2 * i]     = __halves2half2(__float2half(v.x), __float2half(v.y));
        D[2 * i + 1] = __halves2half2(__float2half(v.z), __float2half(v.w));
    }
}

// Split kernel: fp32 -> (hi, lo) fp16 pair.  a = hi + lo + O(2^-22 |a|)
__global__ void __launch_bounds__(256) split_half_kernel(
    const float* __restrict__ src,
    __half* __restrict__ hi, __half* __restrict__ lo, int n4)
{
    for (int i = blockIdx.x * blockDim.x + threadIdx.x; i < n4;
         i += gridDim.x * blockDim.x) {
        const float4 v = ((const float4*)src)[i];
        const float vv[4] = {v.x, v.y, v.z, v.w};
        __half h[4], l[4];
#pragma unroll
        for (int q = 0; q < 4; q++) {
            h[q] = __float2half(vv[q]);
            l[q] = __float2half(vv[q] - __half2float(h[q]));
        }
        __half2* H = (__half2*)hi;
        __half2* L = (__half2*)lo;
        H[2 * i]     = __halves2half2(h[0], h[1]);
        H[2 * i + 1] = __halves2half2(h[2], h[3]);
        L[2 * i]     = __halves2half2(l[0], l[1]);
        L[2 * i + 1] = __halves2half2(l[2], l[3]);
    }
}

__device__ __forceinline__ void mma_f16(
    float& c0, float& c1, float& c2, float& c3,
    uint32_t a0, uint32_t a1, uint32_t a2, uint32_t a3,
    uint32_t b0, uint32_t b1)
{
    asm volatile(
        "mma.sync.aligned.m16n8k16.row.col.f32.f16.f16.f32 "
        "{%0,%1,%2,%3}, {%4,%5,%6,%7}, {%8,%9}, {%0,%1,%2,%3};"
        : "+f"(c0), "+f"(c1), "+f"(c2), "+f"(c3)
        : "r"(a0), "r"(a1), "r"(a2), "r"(a3), "r"(b0), "r"(b1));
}

// ---------------------------------------------------------------------------
// Projection GEMM: C[m][n] = sum_k x[m][k] * Wcat[n][k] (+bias)
// fp16 split-2: A (x) rounded once; W split hi/lo. 2 mma passes:
//   Ah*Wh + Ah*Wl  (= Ah*W exactly; only error is x-rounding ~2^-12)
// Tile/fragments identical to the R10-verified layout.
// ---------------------------------------------------------------------------
#define GSTR   40
#define SA_BUF (128 * GSTR)
#define SB_BUF (64 * GSTR)
#define GSMEM  ((2 * SA_BUF + 2 * SB_BUF * 2) * 2)   // 40960 bytes

__global__ void __launch_bounds__(256, 2) gemm_kernel(
    const float* __restrict__ b_cx, const float* __restrict__ b_ix,
    const float* __restrict__ b_fx)
{
    extern __shared__ __half gsm[];
    __half* sAh = gsm;                          // [2][SA_BUF]
    __half* sBh = gsm + 2 * SA_BUF;             // [2][SB_BUF]
    __half* sBl = gsm + 2 * SA_BUF + 2 * SB_BUF;

    const int tid   = threadIdx.x;
    const int lane  = tid & 31;
    const int warp  = tid >> 5;
    const int warpM = warp & 3;
    const int warpN = warp >> 2;
    const int g     = lane >> 2;
    const int tg    = lane & 3;

    const int mBase = blockIdx.y * 128;
    const int nGlob = blockIdx.x * 64;
    const int mat   = nGlob >> 10;
    const int nMat  = nGlob & 1023;

    const int lr = tid >> 2;
    const int lc = (tid & 3) * 8;
    const size_t aOff0 = (size_t)(mBase + lr) * DIN + lc;
    const size_t aOff1 = (size_t)(mBase + 64 + lr) * DIN + lc;
    const size_t bOff  = (size_t)(nGlob + lr) * DIN + lc;

    float acc[2][4][4];
#pragma unroll
    for (int mt = 0; mt < 2; mt++)
#pragma unroll
        for (int nt = 0; nt < 4; nt++)
#pragma unroll
            for (int q = 0; q < 4; q++) acc[mt][nt][q] = 0.f;

    uint4 rah0 = *(const uint4*)(g_xh + aOff0);
    uint4 rah1 = *(const uint4*)(g_xh + aOff1);
    uint4 rbh  = *(const uint4*)(g_wh + bOff);
    uint4 rbl  = *(const uint4*)(g_wl + bOff);
    {
        const int sa = lr * GSTR + lc;
        *(uint4*)(sAh + sa) = rah0;
        *(uint4*)(sAh + sa + 64 * GSTR) = rah1;
        *(uint4*)(sBh + sa) = rbh;
        *(uint4*)(sBl + sa) = rbl;
    }
    __syncthreads();

    const int aRowOff0 = (warpM * 32 + g) * GSTR;
    const int bColOff  = (warpN * 32 + g) * GSTR;

#pragma unroll 1
    for (int s = 0; s < 32; s++) {
        const int cur = s & 1;
        const __half* Ah = sAh + cur * SA_BUF;
        const __half* Bh = sBh + cur * SB_BUF;
        const __half* Bl = sBl + cur * SB_BUF;

        if (s < 31) {
            const int k0 = (s + 1) * 32;
            rah0 = *(const uint4*)(g_xh + aOff0 + k0);
            rah1 = *(const uint4*)(g_xh + aOff1 + k0);
            rbh  = *(const uint4*)(g_wh + bOff + k0);
            rbl  = *(const uint4*)(g_wl + bOff + k0);
        }

#pragma unroll
        for (int kk = 0; kk < 32; kk += 16) {
            uint32_t fah[2][4], fbh[4][2], fbl[4][2];
#pragma unroll
            for (int mt = 0; mt < 2; mt++) {
                const int r = aRowOff0 + mt * 16 * GSTR + kk + tg * 2;
                fah[mt][0] = *(const uint32_t*)(Ah + r);
                fah[mt][1] = *(const uint32_t*)(Ah + r + 8 * GSTR);
                fah[mt][2] = *(const uint32_t*)(Ah + r + 8);
                fah[mt][3] = *(const uint32_t*)(Ah + r + 8 * GSTR + 8);
            }
#pragma unroll
            for (int nt = 0; nt < 4; nt++) {
                const int c = bColOff + nt * 8 * GSTR + kk + tg * 2;
                fbh[nt][0] = *(const uint32_t*)(Bh + c);
                fbh[nt][1] = *(const uint32_t*)(Bh + c + 8);
                fbl[nt][0] = *(const uint32_t*)(Bl + c);
                fbl[nt][1] = *(const uint32_t*)(Bl + c + 8);
            }
#pragma unroll
            for (int mt = 0; mt < 2; mt++)
#pragma unroll
                for (int nt = 0; nt < 4; nt++) {
                    mma_f16(acc[mt][nt][0], acc[mt][nt][1],
                            acc[mt][nt][2], acc[mt][nt][3],
                            fah[mt][0], fah[mt][1], fah[mt][2], fah[mt][3],
                            fbh[nt][0], fbh[nt][1]);
                    mma_f16(acc[mt][nt][0], acc[mt][nt][1],
                            acc[mt][nt][2], acc[mt][nt][3],
                            fah[mt][0], fah[mt][1], fah[mt][2], fah[mt][3],
                            fbl[nt][0], fbl[nt][1]);
                }
        }

        if (s < 31) {
            const int nxt = cur ^ 1;
            const int sa = lr * GSTR + lc;
            *(uint4*)(sAh + nxt * SA_BUF + sa) = rah0;
            *(uint4*)(sAh + nxt * SA_BUF + sa + 64 * GSTR) = rah1;
            *(uint4*)(sBh + nxt * SB_BUF + sa) = rbh;
            *(uint4*)(sBl + nxt * SB_BUF + sa) = rbl;
            __syncthreads();
        }
    }

    float* dst = (mat == 0) ? g_ct : ((mat == 1) ? g_ix : g_fx);
    const float* bias = (mat == 0) ? b_cx : ((mat == 1) ? b_ix : b_fx);
#pragma unroll
    for (int mt = 0; mt < 2; mt++)
#pragma unroll
        for (int nt = 0; nt < 4; nt++) {
            const int col = nMat + warpN * 32 + nt * 8 + tg * 2;
            const float2 bb = *(const float2*)(bias + col);
            const int r0 = mBase + warpM * 32 + mt * 16 + g;
            float2 o0 = {acc[mt][nt][0] + bb.x, acc[mt][nt][1] + bb.y};
            float2 o1 = {acc[mt][nt][2] + bb.x, acc[mt][nt][3] + bb.y};
            *(float2*)(dst + (size_t)r0 * DH + col) = o0;
            *(float2*)(dst + (size_t)(r0 + 8) * DH + col) = o1;
        }
}

// ---------------------------------------------------------------------------
// HMMA recurrence (R13-verified structure), fp16 split-2:
// h rounded to fp16 each step; gate weights split hi/lo in smem.
// 8 mma/warp/stage (was 12). Per block per step: 2.1M issued MAC = 8.2K cyc.
// ---------------------------------------------------------------------------
#define RBLOCKS   128
#define RTHREADS  512
#define HC_STR    136
#define HC_ELEM   (64 * HC_STR)
#define WB_STR    1032
// smem byte offsets (fp16 = 2B)
#define OFF_WBH   0                        // [16][1032] = 33024
#define OFF_WBL   33024
#define OFF_HSH   66048                    // 2 x [64][136] = 34816
#define OFF_SCR   100864                   // 8*32*5 f32 = 5120
#define OFF_PB    105984                   // [64][18] f32 = 4608
#define MSMEM     110592

__global__ void __launch_bounds__(RTHREADS) recur_mma_kernel(
    const float* __restrict__ h0,
    const float* __restrict__ w_ic, const float* __restrict__ w_fc,
    const float* __restrict__ b_ic, const float* __restrict__ b_fc,
    float* __restrict__ out)
{
    extern __shared__ __align__(16) char smc[];
    __half* wbh = (__half*)(smc + OFF_WBH);
    __half* wbl = (__half*)(smc + OFF_WBL);
    __half* hsh = (__half*)(smc + OFF_HSH);
    float* scr = (float*)(smc + OFF_SCR);
    float* pbf = (float*)(smc + OFF_PB);

    const int tid  = threadIdx.x;
    const int wid  = tid >> 5;
    const int lane = tid & 31;
    const int g    = lane >> 2;
    const int tg   = lane & 3;
    const int mt   = wid & 3;
    const int ntk  = (wid >> 2) & 1;
    const int kc2  = wid >> 3;
    const int jb   = blockIdx.x;

    const int erow = tid >> 3;
    const int ecol = tid & 7;
    const int colg = jb * 8 + ecol;
    const float bi = b_ic[colg];
    const float bf = b_fc[colg];

    // ---- load + split gate weights to smem fp16 hi/lo: n = gate*8 + r ----
    for (int i = tid; i < 16 * 256; i += RTHREADS) {
        const int n = i >> 8;
        const int o = (i & 255) * 4;
        const float* ws = (n < 8 ? w_ic + (size_t)(jb * 8 + n) * DH
                                 : w_fc + (size_t)(jb * 8 + n - 8) * DH) + o;
        const float4 v = *(const float4*)ws;
        const float vv[4] = {v.x, v.y, v.z, v.w};
        __half* dh = wbh + n * WB_STR + o;
        __half* dl = wbl + n * WB_STR + o;
#pragma unroll
        for (int q = 0; q < 4; q++) {
            const __half h = __float2half(vv[q]);
            dh[q] = h;
            dl[q] = __float2half(vv[q] - __half2float(h));
        }
    }

    // ---- prologue: convert this block's h0 cols to fp16 ----
    {
        const float v = h0[(size_t)erow * DH + colg];
        g_hh[(size_t)erow * DH + colg] = __float2half(v);
    }
    const unsigned nb = gridDim.x;
    __threadfence();
    __syncthreads();
    if (tid == 0) {
        atomicAdd(&g_bar, 1u);
        while (*((volatile unsigned*)&g_bar) < nb) { }
        __threadfence();
    }
    __syncthreads();

    const int frow = tid >> 4;             // 0..31 (+32 for second half)
    const int fkq  = (tid & 15) * 8;

    const float* hprev = h0;

#pragma unroll 1
    for (int t = 0; t < T_STEPS; t++) {
        const size_t ob = (size_t)t * (BATCH * DH);

        const size_t ebase = ob + (size_t)erow * DH + colg;
        const float e_ix = g_ix[ebase];
        const float e_fx = g_fx[ebase];
        const float e_ct = g_ct[ebase];
        const float e_hp = hprev[(size_t)erow * DH + colg];

        float acc0 = 0.f, acc1 = 0.f, acc2 = 0.f, acc3 = 0.f;

        uint4 ph0 = *(const uint4*)(g_hh + (size_t)frow * DH + fkq);
        uint4 ph1 = *(const uint4*)(g_hh + (size_t)(frow + 32) * DH + fkq);
        *(uint4*)(hsh + frow * HC_STR + fkq) = ph0;
        *(uint4*)(hsh + (frow + 32) * HC_STR + fkq) = ph1;
        __syncthreads();

#pragma unroll 1
        for (int s = 0; s < 8; s++) {
            const int cb = (s & 1) * HC_ELEM;
            if (s < 7) {
                const int kn = (s + 1) * 128 + fkq;
                ph0 = *(const uint4*)(g_hh + (size_t)frow * DH + kn);
                ph1 = *(const uint4*)(g_hh + (size_t)(frow + 32) * DH + kn);
            }

            const int kb = kc2 * 64;
            const int kw = s * 128 + kc2 * 64;
            const int ar = (mt * 16 + g) * HC_STR;
            const int br = (ntk * 8 + g) * WB_STR;
#pragma unroll
            for (int k4 = 0; k4 < 4; k4++) {
                const int ko = kb + k4 * 16 + tg * 2;
                const int kwo = kw + k4 * 16 + tg * 2;
                const uint32_t ah0 = *(const uint32_t*)(hsh + cb + ar + ko);
                const uint32_t ah1 = *(const uint32_t*)(hsh + cb + ar + 8 * HC_STR + ko);
                const uint32_t ah2 = *(const uint32_t*)(hsh + cb + ar + ko + 8);
                const uint32_t ah3 = *(const uint32_t*)(hsh + cb + ar + 8 * HC_STR + ko + 8);
                const uint32_t bh0 = *(const uint32_t*)(wbh + br + kwo);
                const uint32_t bh1 = *(const uint32_t*)(wbh + br + kwo + 8);
                const uint32_t bl0 = *(const uint32_t*)(wbl + br + kwo);
                const uint32_t bl1 = *(const uint32_t*)(wbl + br + kwo + 8);
                mma_f16(acc0, acc1, acc2, acc3, ah0, ah1, ah2, ah3, bh0, bh1);
                mma_f16(acc0, acc1, acc2, acc3, ah0, ah1, ah2, ah3, bl0, bl1);
            }

            if (s < 7) {
                const int nb2 = ((s + 1) & 1) * HC_ELEM;
                *(uint4*)(hsh + nb2 + frow * HC_STR + fkq) = ph0;
                *(uint4*)(hsh + nb2 + (frow + 32) * HC_STR + fkq) = ph1;
                __syncthreads();
            }
        }

        // ---- kc2 reduction ----
        __syncthreads();
        if (kc2 == 1) {
            const int slot = ((wid - 8) * 32 + lane) * 5;
            scr[slot + 0] = acc0; scr[slot + 1] = acc1;
            scr[slot + 2] = acc2; scr[slot + 3] = acc3;
        }
        __syncthreads();
        if (kc2 == 0) {
            const int slot = (wid * 32 + lane) * 5;
            acc0 += scr[slot + 0]; acc1 += scr[slot + 1];
            acc2 += scr[slot + 2]; acc3 += scr[slot + 3];
            const int r0 = mt * 16 + g;
            const int cc = ntk * 8 + tg * 2;
            *(float2*)(pbf + r0 * 18 + cc) = make_float2(acc0, acc1);
            *(float2*)(pbf + (r0 + 8) * 18 + cc) = make_float2(acc2, acc3);
        }
        __syncthreads();

        // ---- per-thread epilogue ----
        {
            const float pi = pbf[erow * 18 + ecol] + bi + e_ix;
            const float pv = pbf[erow * 18 + ecol + 8] + bf + e_fx;
            const float ig = 1.f / (1.f + expf(-pi));
            const float fg = 1.f / (1.f + expf(-pv));
            const float cc = ig * e_ct + fg * e_hp;
            const float hn = tanhf(cc);
            out[ebase] = hn;
            if (t == T_STEPS - 1) {
                out[(size_t)T_STEPS * BATCH * DH + (size_t)erow * DH + colg] = hn;
            }
            g_hh[(size_t)erow * DH + colg] = __float2half(hn);
        }

        // ---- grid-wide barrier ----
        __threadfence();
        __syncthreads();
        if (tid == 0) {
            atomicAdd(&g_bar, 1u);
            const unsigned target = (unsigned)(t + 2) * nb;
            while (*((volatile unsigned*)&g_bar) < target) { }
            __threadfence();
        }
        __syncthreads();

        hprev = out + ob;
    }
}

// ---------------------------------------------------------------------------
extern "C" void kernel_launch(void* const* d_in, const int* in_sizes, int n_in,
                              void* d_out, int out_size)
{
    const float* x    = (const float*)d_in[0];
    const float* h0   = (const float*)d_in[1];
    const float* w_cx = (const float*)d_in[2];
    const float* w_ic = (const float*)d_in[3];
    const float* w_ix = (const float*)d_in[4];
    const float* w_fc = (const float*)d_in[5];
    const float* w_fx = (const float*)d_in[6];
    const float* b_cx = (const float*)d_in[7];
    const float* b_ic = (const float*)d_in[8];
    const float* b_ix = (const float*)d_in[9];
    const float* b_fc = (const float*)d_in[10];
    const float* b_fx = (const float*)d_in[11];
    float* out = (float*)d_out;

    // reset grid-barrier counter
    void* barAddr = nullptr;
    cudaGetSymbolAddress(&barAddr, g_bar);
    cudaMemsetAsync(barAddr, 0, sizeof(unsigned), 0);

    void *xh, *wh, *wl;
    cudaGetSymbolAddress(&xh, g_xh);
    cudaGetSymbolAddress(&wh, g_wh);
    cudaGetSymbolAddress(&wl, g_wl);

    // 1) x -> fp16 (round once); weights -> fp16 hi/lo
    cvt_half_kernel<<<2048, 256>>>(x, (__half*)xh, (NROWS * DIN) / 4);
    const int wn4 = (DH * DIN) / 4;
    split_half_kernel<<<512, 256>>>(w_cx, (__half*)wh, (__half*)wl, wn4);
    split_half_kernel<<<512, 256>>>(w_ix, (__half*)wh + (size_t)DH * DIN,
                                    (__half*)wl + (size_t)DH * DIN, wn4);
    split_half_kernel<<<512, 256>>>(w_fx, (__half*)wh + (size_t)2 * DH * DIN,
                                    (__half*)wl + (size_t)2 * DH * DIN, wn4);

    // 2) fp16 split-2 projection GEMM
    cudaFuncSetAttribute(gemm_kernel,
                         cudaFuncAttributeMaxDynamicSharedMemorySize, GSMEM);
    dim3 ggrid(3 * DH / 64, NROWS / 128);
    gemm_kernel<<<ggrid, 256, GSMEM>>>(b_cx, b_ix, b_fx);

    // 3) fp16 split-2 HMMA persistent recurrence
    cudaFuncSetAttribute(recur_mma_kernel,
                         cudaFuncAttributeMaxDynamicSharedMemorySize, MSMEM);
    recur_mma_kernel<<<RBLOCKS, RTHREADS, MSMEM>>>(h0, w_ic, w_fc, b_ic, b_fc, out);
}

// round 17
// speedup vs baseline: 2.3019x; 1.0955x over previous
#include <cuda_runtime.h>
#include <cuda_fp16.h>
#include <math.h>
#include <stdint.h>

#define T_STEPS 512
#define BATCH   64
#define DH      1024
#define DIN     1024
#define NROWS   (T_STEPS * BATCH)        // 32768

// proj outputs (ctilde, ix, fx), each [T,B,H] f32.
__device__ float g_ct[(size_t)NROWS * DH];
__device__ float g_ix[(size_t)NROWS * DH];
__device__ float g_fx[(size_t)NROWS * DH];
__device__ unsigned g_bar;

// fp16 scratch: x (rounded once), proj weights (rounded once), per-step h
__device__ __half g_xh[(size_t)NROWS * DIN];
__device__ __half g_wh[(size_t)3 * DH * DIN];
__device__ __half g_hh[(size_t)BATCH * DH];

// ---------------------------------------------------------------------------
// Convert kernel: fp32 -> fp16 (round once; error 2^-12 rms relative)
// ---------------------------------------------------------------------------
__global__ void __launch_bounds__(256) cvt_half_kernel(
    const float* __restrict__ src, __half* __restrict__ dst, int n4)
{
    for (int i = blockIdx.x * blockDim.x + threadIdx.x; i < n4;
         i += gridDim.x * blockDim.x) {
        const float4 v = ((const float4*)src)[i];
        __half2* D = (__half2*)dst;
        D[2 * i]     = __halves2half2(__float2half(v.x), __float2half(v.y));
        D[2 * i + 1] = __halves2half2(__float2half(v.z), __float2half(v.w));
    }
}

__device__ __forceinline__ void mma_f16(
    float& c0, float& c1, float& c2, float& c3,
    uint32_t a0, uint32_t a1, uint32_t a2, uint32_t a3,
    uint32_t b0, uint32_t b1)
{
    asm volatile(
        "mma.sync.aligned.m16n8k16.row.col.f32.f16.f16.f32 "
        "{%0,%1,%2,%3}, {%4,%5,%6,%7}, {%8,%9}, {%0,%1,%2,%3};"
        : "+f"(c0), "+f"(c1), "+f"(c2), "+f"(c3)
        : "r"(a0), "r"(a1), "r"(a2), "r"(a3), "r"(b0), "r"(b1));
}

// ---------------------------------------------------------------------------
// Projection GEMM: C[m][n] = sum_k x[m][k] * Wcat[n][k] (+bias)
// Single-pass fp16 (x and W each rounded once; fp32 accumulate).
// Proj error is non-compounding (enters each gate once); the compounding
// recurrence path below keeps its weights split-exact.
// Tile/fragments identical to the R10-verified layout.
// ---------------------------------------------------------------------------
#define GSTR   40
#define SA_BUF (128 * GSTR)
#define SB_BUF (64 * GSTR)
#define GSMEM  ((2 * SA_BUF + 2 * SB_BUF) * 2)   // 30720 bytes

__global__ void __launch_bounds__(256, 2) gemm_kernel(
    const float* __restrict__ b_cx, const float* __restrict__ b_ix,
    const float* __restrict__ b_fx)
{
    extern __shared__ __half gsm[];
    __half* sAh = gsm;                          // [2][SA_BUF]
    __half* sBh = gsm + 2 * SA_BUF;             // [2][SB_BUF]

    const int tid   = threadIdx.x;
    const int lane  = tid & 31;
    const int warp  = tid >> 5;
    const int warpM = warp & 3;
    const int warpN = warp >> 2;
    const int g     = lane >> 2;
    const int tg    = lane & 3;

    const int mBase = blockIdx.y * 128;
    const int nGlob = blockIdx.x * 64;
    const int mat   = nGlob >> 10;
    const int nMat  = nGlob & 1023;

    const int lr = tid >> 2;
    const int lc = (tid & 3) * 8;
    const size_t aOff0 = (size_t)(mBase + lr) * DIN + lc;
    const size_t aOff1 = (size_t)(mBase + 64 + lr) * DIN + lc;
    const size_t bOff  = (size_t)(nGlob + lr) * DIN + lc;

    float acc[2][4][4];
#pragma unroll
    for (int mt = 0; mt < 2; mt++)
#pragma unroll
        for (int nt = 0; nt < 4; nt++)
#pragma unroll
            for (int q = 0; q < 4; q++) acc[mt][nt][q] = 0.f;

    uint4 rah0 = *(const uint4*)(g_xh + aOff0);
    uint4 rah1 = *(const uint4*)(g_xh + aOff1);
    uint4 rbh  = *(const uint4*)(g_wh + bOff);
    {
        const int sa = lr * GSTR + lc;
        *(uint4*)(sAh + sa) = rah0;
        *(uint4*)(sAh + sa + 64 * GSTR) = rah1;
        *(uint4*)(sBh + sa) = rbh;
    }
    __syncthreads();

    const int aRowOff0 = (warpM * 32 + g) * GSTR;
    const int bColOff  = (warpN * 32 + g) * GSTR;

#pragma unroll 1
    for (int s = 0; s < 32; s++) {
        const int cur = s & 1;
        const __half* Ah = sAh + cur * SA_BUF;
        const __half* Bh = sBh + cur * SB_BUF;

        if (s < 31) {
            const int k0 = (s + 1) * 32;
            rah0 = *(const uint4*)(g_xh + aOff0 + k0);
            rah1 = *(const uint4*)(g_xh + aOff1 + k0);
            rbh  = *(const uint4*)(g_wh + bOff + k0);
        }

#pragma unroll
        for (int kk = 0; kk < 32; kk += 16) {
            uint32_t fah[2][4], fbh[4][2];
#pragma unroll
            for (int mt = 0; mt < 2; mt++) {
                const int r = aRowOff0 + mt * 16 * GSTR + kk + tg * 2;
                fah[mt][0] = *(const uint32_t*)(Ah + r);
                fah[mt][1] = *(const uint32_t*)(Ah + r + 8 * GSTR);
                fah[mt][2] = *(const uint32_t*)(Ah + r + 8);
                fah[mt][3] = *(const uint32_t*)(Ah + r + 8 * GSTR + 8);
            }
#pragma unroll
            for (int nt = 0; nt < 4; nt++) {
                const int c = bColOff + nt * 8 * GSTR + kk + tg * 2;
                fbh[nt][0] = *(const uint32_t*)(Bh + c);
                fbh[nt][1] = *(const uint32_t*)(Bh + c + 8);
            }
#pragma unroll
            for (int mt = 0; mt < 2; mt++)
#pragma unroll
                for (int nt = 0; nt < 4; nt++) {
                    mma_f16(acc[mt][nt][0], acc[mt][nt][1],
                            acc[mt][nt][2], acc[mt][nt][3],
                            fah[mt][0], fah[mt][1], fah[mt][2], fah[mt][3],
                            fbh[nt][0], fbh[nt][1]);
                }
        }

        if (s < 31) {
            const int nxt = cur ^ 1;
            const int sa = lr * GSTR + lc;
            *(uint4*)(sAh + nxt * SA_BUF + sa) = rah0;
            *(uint4*)(sAh + nxt * SA_BUF + sa + 64 * GSTR) = rah1;
            *(uint4*)(sBh + nxt * SB_BUF + sa) = rbh;
            __syncthreads();
        }
    }

    float* dst = (mat == 0) ? g_ct : ((mat == 1) ? g_ix : g_fx);
    const float* bias = (mat == 0) ? b_cx : ((mat == 1) ? b_ix : b_fx);
#pragma unroll
    for (int mt = 0; mt < 2; mt++)
#pragma unroll
        for (int nt = 0; nt < 4; nt++) {
            const int col = nMat + warpN * 32 + nt * 8 + tg * 2;
            const float2 bb = *(const float2*)(bias + col);
            const int r0 = mBase + warpM * 32 + mt * 16 + g;
            float2 o0 = {acc[mt][nt][0] + bb.x, acc[mt][nt][1] + bb.y};
            float2 o1 = {acc[mt][nt][2] + bb.x, acc[mt][nt][3] + bb.y};
            *(float2*)(dst + (size_t)r0 * DH + col) = o0;
            *(float2*)(dst + (size_t)(r0 + 8) * DH + col) = o1;
        }
}

// ---------------------------------------------------------------------------
// HMMA recurrence (R13/R16-verified structure), fp16 split-2:
// h rounded to fp16 each step; gate weights split hi/lo in smem (W exact —
// this is the compounding path, so it keeps the extra pass).
// ---------------------------------------------------------------------------
#define RBLOCKS   128
#define RTHREADS  512
#define HC_STR    136
#define HC_ELEM   (64 * HC_STR)
#define WB_STR    1032
// smem byte offsets (fp16 = 2B)
#define OFF_WBH   0                        // [16][1032] = 33024
#define OFF_WBL   33024
#define OFF_HSH   66048                    // 2 x [64][136] = 34816
#define OFF_SCR   100864                   // 8*32*5 f32 = 5120
#define OFF_PB    105984                   // [64][18] f32 = 4608
#define MSMEM     110592

__global__ void __launch_bounds__(RTHREADS) recur_mma_kernel(
    const float* __restrict__ h0,
    const float* __restrict__ w_ic, const float* __restrict__ w_fc,
    const float* __restrict__ b_ic, const float* __restrict__ b_fc,
    float* __restrict__ out)
{
    extern __shared__ __align__(16) char smc[];
    __half* wbh = (__half*)(smc + OFF_WBH);
    __half* wbl = (__half*)(smc + OFF_WBL);
    __half* hsh = (__half*)(smc + OFF_HSH);
    float* scr = (float*)(smc + OFF_SCR);
    float* pbf = (float*)(smc + OFF_PB);

    const int tid  = threadIdx.x;
    const int wid  = tid >> 5;
    const int lane = tid & 31;
    const int g    = lane >> 2;
    const int tg   = lane & 3;
    const int mt   = wid & 3;
    const int ntk  = (wid >> 2) & 1;
    const int kc2  = wid >> 3;
    const int jb   = blockIdx.x;

    const int erow = tid >> 3;
    const int ecol = tid & 7;
    const int colg = jb * 8 + ecol;
    const float bi = b_ic[colg];
    const float bf = b_fc[colg];

    // ---- load + split gate weights to smem fp16 hi/lo: n = gate*8 + r ----
    for (int i = tid; i < 16 * 256; i += RTHREADS) {
        const int n = i >> 8;
        const int o = (i & 255) * 4;
        const float* ws = (n < 8 ? w_ic + (size_t)(jb * 8 + n) * DH
                                 : w_fc + (size_t)(jb * 8 + n - 8) * DH) + o;
        const float4 v = *(const float4*)ws;
        const float vv[4] = {v.x, v.y, v.z, v.w};
        __half* dh = wbh + n * WB_STR + o;
        __half* dl = wbl + n * WB_STR + o;
#pragma unroll
        for (int q = 0; q < 4; q++) {
            const __half h = __float2half(vv[q]);
            dh[q] = h;
            dl[q] = __float2half(vv[q] - __half2float(h));
        }
    }

    // ---- prologue: convert this block's h0 cols to fp16 ----
    {
        const float v = h0[(size_t)erow * DH + colg];
        g_hh[(size_t)erow * DH + colg] = __float2half(v);
    }
    const unsigned nb = gridDim.x;
    __threadfence();
    __syncthreads();
    if (tid == 0) {
        atomicAdd(&g_bar, 1u);
        while (*((volatile unsigned*)&g_bar) < nb) { }
        __threadfence();
    }
    __syncthreads();

    const int frow = tid >> 4;             // 0..31 (+32 for second half)
    const int fkq  = (tid & 15) * 8;

    const float* hprev = h0;

#pragma unroll 1
    for (int t = 0; t < T_STEPS; t++) {
        const size_t ob = (size_t)t * (BATCH * DH);

        const size_t ebase = ob + (size_t)erow * DH + colg;
        const float e_ix = g_ix[ebase];
        const float e_fx = g_fx[ebase];
        const float e_ct = g_ct[ebase];
        const float e_hp = hprev[(size_t)erow * DH + colg];

        float acc0 = 0.f, acc1 = 0.f, acc2 = 0.f, acc3 = 0.f;

        uint4 ph0 = *(const uint4*)(g_hh + (size_t)frow * DH + fkq);
        uint4 ph1 = *(const uint4*)(g_hh + (size_t)(frow + 32) * DH + fkq);
        *(uint4*)(hsh + frow * HC_STR + fkq) = ph0;
        *(uint4*)(hsh + (frow + 32) * HC_STR + fkq) = ph1;
        __syncthreads();

#pragma unroll 1
        for (int s = 0; s < 8; s++) {
            const int cb = (s & 1) * HC_ELEM;
            if (s < 7) {
                const int kn = (s + 1) * 128 + fkq;
                ph0 = *(const uint4*)(g_hh + (size_t)frow * DH + kn);
                ph1 = *(const uint4*)(g_hh + (size_t)(frow + 32) * DH + kn);
            }

            const int kb = kc2 * 64;
            const int kw = s * 128 + kc2 * 64;
            const int ar = (mt * 16 + g) * HC_STR;
            const int br = (ntk * 8 + g) * WB_STR;
#pragma unroll
            for (int k4 = 0; k4 < 4; k4++) {
                const int ko = kb + k4 * 16 + tg * 2;
                const int kwo = kw + k4 * 16 + tg * 2;
                const uint32_t ah0 = *(const uint32_t*)(hsh + cb + ar + ko);
                const uint32_t ah1 = *(const uint32_t*)(hsh + cb + ar + 8 * HC_STR + ko);
                const uint32_t ah2 = *(const uint32_t*)(hsh + cb + ar + ko + 8);
                const uint32_t ah3 = *(const uint32_t*)(hsh + cb + ar + 8 * HC_STR + ko + 8);
                const uint32_t bh0 = *(const uint32_t*)(wbh + br + kwo);
                const uint32_t bh1 = *(const uint32_t*)(wbh + br + kwo + 8);
                const uint32_t bl0 = *(const uint32_t*)(wbl + br + kwo);
                const uint32_t bl1 = *(const uint32_t*)(wbl + br + kwo + 8);
                mma_f16(acc0, acc1, acc2, acc3, ah0, ah1, ah2, ah3, bh0, bh1);
                mma_f16(acc0, acc1, acc2, acc3, ah0, ah1, ah2, ah3, bl0, bl1);
            }

            if (s < 7) {
                const int nb2 = ((s + 1) & 1) * HC_ELEM;
                *(uint4*)(hsh + nb2 + frow * HC_STR + fkq) = ph0;
                *(uint4*)(hsh + nb2 + (frow + 32) * HC_STR + fkq) = ph1;
                __syncthreads();
            }
        }

        // ---- kc2 reduction ----
        __syncthreads();
        if (kc2 == 1) {
            const int slot = ((wid - 8) * 32 + lane) * 5;
            scr[slot + 0] = acc0; scr[slot + 1] = acc1;
            scr[slot + 2] = acc2; scr[slot + 3] = acc3;
        }
        __syncthreads();
        if (kc2 == 0) {
            const int slot = (wid * 32 + lane) * 5;
            acc0 += scr[slot + 0]; acc1 += scr[slot + 1];
            acc2 += scr[slot + 2]; acc3 += scr[slot + 3];
            const int r0 = mt * 16 + g;
            const int cc = ntk * 8 + tg * 2;
            *(float2*)(pbf + r0 * 18 + cc) = make_float2(acc0, acc1);
            *(float2*)(pbf + (r0 + 8) * 18 + cc) = make_float2(acc2, acc3);
        }
        __syncthreads();

        // ---- per-thread epilogue ----
        {
            const float pi = pbf[erow * 18 + ecol] + bi + e_ix;
            const float pv = pbf[erow * 18 + ecol + 8] + bf + e_fx;
            const float ig = 1.f / (1.f + expf(-pi));
            const float fg = 1.f / (1.f + expf(-pv));
            const float cc = ig * e_ct + fg * e_hp;
            const float hn = tanhf(cc);
            out[ebase] = hn;
            if (t == T_STEPS - 1) {
                out[(size_t)T_STEPS * BATCH * DH + (size_t)erow * DH + colg] = hn;
            }
            g_hh[(size_t)erow * DH + colg] = __float2half(hn);
        }

        // ---- grid-wide barrier ----
        __threadfence();
        __syncthreads();
        if (tid == 0) {
            atomicAdd(&g_bar, 1u);
            const unsigned target = (unsigned)(t + 2) * nb;
            while (*((volatile unsigned*)&g_bar) < target) { }
            __threadfence();
        }
        __syncthreads();

        hprev = out + ob;
    }
}

// ---------------------------------------------------------------------------
extern "C" void kernel_launch(void* const* d_in, const int* in_sizes, int n_in,
                              void* d_out, int out_size)
{
    const float* x    = (const float*)d_in[0];
    const float* h0   = (const float*)d_in[1];
    const float* w_cx = (const float*)d_in[2];
    const float* w_ic = (const float*)d_in[3];
    const float* w_ix = (const float*)d_in[4];
    const float* w_fc = (const float*)d_in[5];
    const float* w_fx = (const float*)d_in[6];
    const float* b_cx = (const float*)d_in[7];
    const float* b_ic = (const float*)d_in[8];
    const float* b_ix = (const float*)d_in[9];
    const float* b_fc = (const float*)d_in[10];
    const float* b_fx = (const float*)d_in[11];
    float* out = (float*)d_out;

    // reset grid-barrier counter
    void* barAddr = nullptr;
    cudaGetSymbolAddress(&barAddr, g_bar);
    cudaMemsetAsync(barAddr, 0, sizeof(unsigned), 0);

    void *xh, *wh;
    cudaGetSymbolAddress(&xh, g_xh);
    cudaGetSymbolAddress(&wh, g_wh);

    // 1) x -> fp16, weights -> fp16 (each rounded once)
    cvt_half_kernel<<<2048, 256>>>(x, (__half*)xh, (NROWS * DIN) / 4);
    const int wn4 = (DH * DIN) / 4;
    cvt_half_kernel<<<512, 256>>>(w_cx, (__half*)wh, wn4);
    cvt_half_kernel<<<512, 256>>>(w_ix, (__half*)wh + (size_t)DH * DIN, wn4);
    cvt_half_kernel<<<512, 256>>>(w_fx, (__half*)wh + (size_t)2 * DH * DIN, wn4);

    // 2) single-pass fp16 projection GEMM
    cudaFuncSetAttribute(gemm_kernel,
                         cudaFuncAttributeMaxDynamicSharedMemorySize, GSMEM);
    dim3 ggrid(3 * DH / 64, NROWS / 128);
    gemm_kernel<<<ggrid, 256, GSMEM>>>(b_cx, b_ix, b_fx);

    // 3) fp16 split-2 HMMA persistent recurrence
    cudaFuncSetAttribute(recur_mma_kernel,
                         cudaFuncAttributeMaxDynamicSharedMemorySize, MSMEM);
    recur_mma_kernel<<<RBLOCKS, RTHREADS, MSMEM>>>(h0, w_ic, w_fc, b_ic, b_fc, out);
}